// round 9
// baseline (speedup 1.0000x reference)
#include <cuda_runtime.h>
#include <cuda_bf16.h>
#include <math.h>

// Problem constants (fixed by setup_inputs)
#define BB 4
#define SS 2048
#define EMB 1024
#define HEADS 16
#define HDIM 64
#define MROWS (BB * SS)   // 8192

// ---------------------------------------------------------------------------
// Scratch: __device__ globals (allocation APIs are forbidden).
// Q/K/V in (B,H,S,D) layout, attn in (B,S,E) layout.
// ---------------------------------------------------------------------------
__device__ float g_q[MROWS * EMB];
__device__ float g_k[MROWS * EMB];
__device__ float g_v[MROWS * EMB];
__device__ float g_attn[MROWS * EMB];

// ---------------------------------------------------------------------------
// SGEMM with bias: C = (A[MxK] @ W[KxN] + bias) * scale
// 128x128 block tile, BK=8, 256 threads, 8x8 per-thread microtile.
// split_mode=1: write to (B,H,S,D) layout (m=b*S+s, n=h*64+d).
// ---------------------------------------------------------------------------
__global__ __launch_bounds__(256) void sgemm_bias(
    const float* __restrict__ A, const float* __restrict__ W,
    const float* __restrict__ bias, float* __restrict__ C,
    int M, int N, int K, float scale, int split_mode)
{
    __shared__ float As[8][128];
    __shared__ float Bs[8][128];

    const int tid = threadIdx.x;
    const int ty  = tid >> 4;          // 0..15 -> row group
    const int tx  = tid & 15;          // 0..15 -> col group
    const int row0 = blockIdx.y * 128;
    const int col0 = blockIdx.x * 128;

    float acc[8][8];
#pragma unroll
    for (int i = 0; i < 8; i++)
#pragma unroll
        for (int j = 0; j < 8; j++) acc[i][j] = 0.f;

    const int arow = tid >> 1;         // 0..127
    const int acol = (tid & 1) * 4;    // 0 or 4
    const int brow = tid >> 5;         // 0..7
    const int bcol = (tid & 31) * 4;   // 0..124

    const float* Ap = A + (size_t)(row0 + arow) * K + acol;
    const float* Bp = W + (size_t)brow * N + col0 + bcol;

    for (int k0 = 0; k0 < K; k0 += 8) {
        float4 av = *(const float4*)Ap;
        float4 bv = *(const float4*)Bp;
        Ap += 8;
        Bp += (size_t)8 * N;

        As[acol + 0][arow] = av.x;
        As[acol + 1][arow] = av.y;
        As[acol + 2][arow] = av.z;
        As[acol + 3][arow] = av.w;
        *(float4*)&Bs[brow][bcol] = bv;
        __syncthreads();

#pragma unroll
        for (int kk = 0; kk < 8; kk++) {
            float a[8], b[8];
            *(float4*)&a[0] = *(float4*)&As[kk][ty * 8];
            *(float4*)&a[4] = *(float4*)&As[kk][ty * 8 + 4];
            *(float4*)&b[0] = *(float4*)&Bs[kk][tx * 8];
            *(float4*)&b[4] = *(float4*)&Bs[kk][tx * 8 + 4];
#pragma unroll
            for (int i = 0; i < 8; i++)
#pragma unroll
                for (int j = 0; j < 8; j++)
                    acc[i][j] += a[i] * b[j];
        }
        __syncthreads();
    }

    // Epilogue
#pragma unroll
    for (int i = 0; i < 8; i++) {
        const int m = row0 + ty * 8 + i;
#pragma unroll
        for (int j = 0; j < 8; j++) {
            const int n = col0 + tx * 8 + j;
            float v = (acc[i][j] + bias[n]) * scale;
            if (split_mode) {
                const int b = m >> 11;       // / 2048
                const int s = m & 2047;
                const int h = n >> 6;        // / 64
                const int d = n & 63;
                C[(((size_t)(b * HEADS + h) * SS) + s) * HDIM + d] = v;
            } else {
                C[(size_t)m * N + n] = v;
            }
        }
    }
}

// ---------------------------------------------------------------------------
// Flash attention: per block one (b,h) and 64 query rows. Online softmax over
// 32 key blocks of 64. D=64. Scale 1/8 already folded into Q.
// smem: Q (16KB) + K (16KB, reused for P) + V (16KB) = 48KB exactly.
// Output written in (B,S,E) layout for the final projection.
//
// Mask: bool widened by the harness to a 32-bit word per element (int32 1/0
// or float32 1.0f/0.0f — both have "nonzero word == true"). Read as uint32.
// ---------------------------------------------------------------------------
__global__ __launch_bounds__(256) void flash_attn64(
    const float* __restrict__ Q, const float* __restrict__ Kg,
    const float* __restrict__ Vg, const unsigned int* __restrict__ mask,
    float* __restrict__ O)
{
    __shared__ float sQ[64 * 64];
    __shared__ float sK[64 * 64];   // reused as P after scores are consumed
    __shared__ float sV[64 * 64];

    const int tid = threadIdx.x;
    const int ty = tid >> 4;       // 0..15 -> 4 query rows
    const int tx = tid & 15;       // 0..15 -> 4 key cols / 4 d cols
    const int bh = blockIdx.y;     // 0..63
    const int b  = bh >> 4;
    const int h  = bh & 15;
    const int q0 = blockIdx.x * 64;

    const float* Qb = Q  + ((size_t)bh * SS + q0) * HDIM;
    const float* Kb = Kg + (size_t)bh * SS * HDIM;
    const float* Vb = Vg + (size_t)bh * SS * HDIM;

    // Load Q tile (contiguous 4096 floats)
#pragma unroll
    for (int i = 0; i < 4; i++) {
        const int j = tid + i * 256;
        *(float4*)&sQ[j * 4] = *(const float4*)&Qb[j * 4];
    }

    float m_i[4], l_i[4], o[4][4];
#pragma unroll
    for (int i = 0; i < 4; i++) {
        m_i[i] = -INFINITY;
        l_i[i] = 0.f;
#pragma unroll
        for (int j = 0; j < 4; j++) o[i][j] = 0.f;
    }

    for (int kb = 0; kb < 32; kb++) {
        __syncthreads();  // Q ready (iter 0); prior P/V reads done
        const float* Kt = Kb + (size_t)kb * 64 * HDIM;
        const float* Vt = Vb + (size_t)kb * 64 * HDIM;
#pragma unroll
        for (int i = 0; i < 4; i++) {
            const int j = tid + i * 256;
            *(float4*)&sK[j * 4] = *(const float4*)&Kt[j * 4];
            *(float4*)&sV[j * 4] = *(const float4*)&Vt[j * 4];
        }
        __syncthreads();

        // Scores: s[i][j] = sum_d Q[ty*4+i][d] * K[tx*4+j][d]
        float s[4][4];
#pragma unroll
        for (int i = 0; i < 4; i++)
#pragma unroll
            for (int j = 0; j < 4; j++) s[i][j] = 0.f;

#pragma unroll 8
        for (int d0 = 0; d0 < 16; d0++) {
            float4 qv[4], kv[4];
#pragma unroll
            for (int i = 0; i < 4; i++)
                qv[i] = *(float4*)&sQ[(ty * 4 + i) * 64 + d0 * 4];
#pragma unroll
            for (int j = 0; j < 4; j++)
                kv[j] = *(float4*)&sK[(tx * 4 + j) * 64 + d0 * 4];
#pragma unroll
            for (int i = 0; i < 4; i++)
#pragma unroll
                for (int j = 0; j < 4; j++) {
                    s[i][j] += qv[i].x * kv[j].x;
                    s[i][j] += qv[i].y * kv[j].y;
                    s[i][j] += qv[i].z * kv[j].z;
                    s[i][j] += qv[i].w * kv[j].w;
                }
        }

        // Mask: one 32-bit word per key position; nonzero = keep.
        {
            const uint4 mk = *(const uint4*)&mask[(size_t)b * SS + kb * 64 + tx * 4];
            const float mb0 = mk.x ? 0.f : -1e30f;
            const float mb1 = mk.y ? 0.f : -1e30f;
            const float mb2 = mk.z ? 0.f : -1e30f;
            const float mb3 = mk.w ? 0.f : -1e30f;
#pragma unroll
            for (int i = 0; i < 4; i++) {
                s[i][0] += mb0; s[i][1] += mb1; s[i][2] += mb2; s[i][3] += mb3;
            }
        }

        // Online softmax per row; row spans 16 threads (same ty) within one
        // half-warp, so xor-shuffles over bits 0..3 stay in-group.
#pragma unroll
        for (int i = 0; i < 4; i++) {
            float rm = fmaxf(fmaxf(s[i][0], s[i][1]), fmaxf(s[i][2], s[i][3]));
            rm = fmaxf(rm, __shfl_xor_sync(0xffffffffu, rm, 1));
            rm = fmaxf(rm, __shfl_xor_sync(0xffffffffu, rm, 2));
            rm = fmaxf(rm, __shfl_xor_sync(0xffffffffu, rm, 4));
            rm = fmaxf(rm, __shfl_xor_sync(0xffffffffu, rm, 8));
            const float nm = fmaxf(m_i[i], rm);
            const float corr = __expf(m_i[i] - nm);
            float rs = 0.f;
#pragma unroll
            for (int j = 0; j < 4; j++) {
                s[i][j] = __expf(s[i][j] - nm);
                rs += s[i][j];
            }
            rs += __shfl_xor_sync(0xffffffffu, rs, 1);
            rs += __shfl_xor_sync(0xffffffffu, rs, 2);
            rs += __shfl_xor_sync(0xffffffffu, rs, 4);
            rs += __shfl_xor_sync(0xffffffffu, rs, 8);
            l_i[i] = l_i[i] * corr + rs;
            m_i[i] = nm;
#pragma unroll
            for (int j = 0; j < 4; j++) o[i][j] *= corr;
        }

        // Write P into the K tile (K fully consumed)
        __syncthreads();
#pragma unroll
        for (int i = 0; i < 4; i++)
            *(float4*)&sK[(ty * 4 + i) * 64 + tx * 4] =
                make_float4(s[i][0], s[i][1], s[i][2], s[i][3]);
        __syncthreads();

        // o[i][:] += sum_k P[row_i][k] * V[k][tx*4 .. tx*4+3]
#pragma unroll 8
        for (int k = 0; k < 64; k++) {
            const float4 vv = *(float4*)&sV[k * 64 + tx * 4];
#pragma unroll
            for (int i = 0; i < 4; i++) {
                const float p = sK[(ty * 4 + i) * 64 + k];
                o[i][0] += p * vv.x;
                o[i][1] += p * vv.y;
                o[i][2] += p * vv.z;
                o[i][3] += p * vv.w;
            }
        }
    }

    // Epilogue: normalize and write (B,S,E)
#pragma unroll
    for (int i = 0; i < 4; i++) {
        const float inv = 1.f / l_i[i];
        const size_t row = (size_t)b * SS + q0 + ty * 4 + i;
        *(float4*)&O[row * EMB + h * HDIM + tx * 4] =
            make_float4(o[i][0] * inv, o[i][1] * inv, o[i][2] * inv, o[i][3] * inv);
    }
}

// ---------------------------------------------------------------------------
// Launch
// Inputs (metadata order): query, key, value, mask, Wq, bq, Wk, bk, Wv, bv, Wo, bo
// ---------------------------------------------------------------------------
extern "C" void kernel_launch(void* const* d_in, const int* in_sizes, int n_in,
                              void* d_out, int out_size)
{
    const float* query = (const float*)d_in[0];
    const float* key   = (const float*)d_in[1];
    const float* value = (const float*)d_in[2];
    const unsigned int* mask = (const unsigned int*)d_in[3];
    const float* Wq = (const float*)d_in[4];
    const float* bq = (const float*)d_in[5];
    const float* Wk = (const float*)d_in[6];
    const float* bk = (const float*)d_in[7];
    const float* Wv = (const float*)d_in[8];
    const float* bv = (const float*)d_in[9];
    const float* Wo = (const float*)d_in[10];
    const float* bo = (const float*)d_in[11];
    float* out = (float*)d_out;

    float *q, *k, *v, *attn;
    cudaGetSymbolAddress((void**)&q,    g_q);
    cudaGetSymbolAddress((void**)&k,    g_k);
    cudaGetSymbolAddress((void**)&v,    g_v);
    cudaGetSymbolAddress((void**)&attn, g_attn);

    const dim3 blk(256);
    const dim3 gemm_grid(EMB / 128, MROWS / 128);   // (8, 64)
    const float qscale = 0.125f;                    // 1/sqrt(64)

    // Projections (split-head layout); fold score scale into Q
    sgemm_bias<<<gemm_grid, blk>>>(query, Wq, bq, q, MROWS, EMB, EMB, qscale, 1);
    sgemm_bias<<<gemm_grid, blk>>>(key,   Wk, bk, k, MROWS, EMB, EMB, 1.0f,  1);
    sgemm_bias<<<gemm_grid, blk>>>(value, Wv, bv, v, MROWS, EMB, EMB, 1.0f,  1);

    // Attention: grid (q-tiles, B*H)
    flash_attn64<<<dim3(SS / 64, BB * HEADS), blk>>>(q, k, v, mask, attn);

    // Output projection straight into d_out
    sgemm_bias<<<gemm_grid, blk>>>(attn, Wo, bo, out, MROWS, EMB, EMB, 1.0f, 0);
}

// round 10
// speedup vs baseline: 1.9396x; 1.9396x over previous
#include <cuda_runtime.h>
#include <cuda_bf16.h>
#include <math.h>

// Problem constants (fixed by setup_inputs)
#define BB 4
#define SS 2048
#define EMB 1024
#define HEADS 16
#define HDIM 64
#define MROWS (BB * SS)   // 8192

typedef unsigned long long u64;

// ---------------------------------------------------------------------------
// Packed f32x2 helpers (ptxas never auto-fuses; PTX-only path on sm_103a)
// ---------------------------------------------------------------------------
__device__ __forceinline__ u64 pk2(float lo, float hi) {
    u64 r; asm("mov.b64 %0, {%1, %2};" : "=l"(r) : "f"(lo), "f"(hi)); return r;
}
__device__ __forceinline__ u64 dup2(float v) {
    u64 r; asm("mov.b64 %0, {%1, %1};" : "=l"(r) : "f"(v)); return r;
}
__device__ __forceinline__ void upk2(u64 v, float& lo, float& hi) {
    asm("mov.b64 {%0, %1}, %2;" : "=f"(lo), "=f"(hi) : "l"(v));
}
__device__ __forceinline__ u64 f2fma(u64 a, u64 b, u64 c) {
    u64 d; asm("fma.rn.f32x2 %0, %1, %2, %3;" : "=l"(d) : "l"(a), "l"(b), "l"(c)); return d;
}
__device__ __forceinline__ u64 f2mul(u64 a, u64 b) {
    u64 d; asm("mul.rn.f32x2 %0, %1, %2;" : "=l"(d) : "l"(a), "l"(b)); return d;
}

// Swizzled float index for a [64 x 64] f32 tile: 16B chunk XOR'd by (row>>2).
// Kills the row-stride-64 same-bank pathology (16-way -> 2-way).
__device__ __forceinline__ int SW(int row, int chunk) {
    return (row << 6) + (((chunk ^ (row >> 2)) & 15) << 2);
}

// ---------------------------------------------------------------------------
// Scratch: __device__ globals (allocation APIs are forbidden).
// ---------------------------------------------------------------------------
__device__ float g_q[MROWS * EMB];
__device__ float g_k[MROWS * EMB];
__device__ float g_v[MROWS * EMB];
__device__ float g_attn[MROWS * EMB];

// ---------------------------------------------------------------------------
// SGEMM with bias: C = (A[MxK] @ W[KxN] + bias) * scale
// 128x128 tile, BK=8, 256 threads. 8x8 per-thread microtile computed as
// 8x4 f32x2 pair-accumulators. Columns split tx*4 / tx*4+64 (2-way LDS floor),
// rows ty*4 / ty*4+64. Register prefetch of the next A/B fragments.
// split_mode=1: write to (B,H,S,D) layout.
// ---------------------------------------------------------------------------
__global__ __launch_bounds__(256) void sgemm_bias(
    const float* __restrict__ A, const float* __restrict__ W,
    const float* __restrict__ bias, float* __restrict__ C,
    int M, int N, int K, float scale, int split_mode)
{
    __shared__ float As[8][128];
    __shared__ float Bs[8][128];

    const int tid = threadIdx.x;
    const int ty  = tid >> 4;          // 0..15
    const int tx  = tid & 15;          // 0..15
    const int row0 = blockIdx.y * 128;
    const int col0 = blockIdx.x * 128;
    const int ty4 = ty * 4, tx4 = tx * 4;

    u64 acc2[8][4];
#pragma unroll
    for (int i = 0; i < 8; i++)
#pragma unroll
        for (int j = 0; j < 4; j++) acc2[i][j] = 0ull;

    const int arow = tid >> 1;
    const int acol = (tid & 1) * 4;
    const int brow = tid >> 5;
    const int bcol = (tid & 31) * 4;

    const float* Ap = A + (size_t)(row0 + arow) * K + acol;
    const float* Bp = W + (size_t)brow * N + col0 + bcol;

    float4 av = *(const float4*)Ap;
    float4 bv = *(const float4*)Bp;

    for (int k0 = 0; k0 < K; k0 += 8) {
        As[acol + 0][arow] = av.x;
        As[acol + 1][arow] = av.y;
        As[acol + 2][arow] = av.z;
        As[acol + 3][arow] = av.w;
        *(float4*)&Bs[brow][bcol] = bv;
        __syncthreads();

        if (k0 + 8 < K) {       // prefetch next fragments under the compute
            Ap += 8;
            Bp += (size_t)8 * N;
            av = *(const float4*)Ap;
            bv = *(const float4*)Bp;
        }

#pragma unroll
        for (int kk = 0; kk < 8; kk++) {
            const float4 a0 = *(const float4*)&As[kk][ty4];
            const float4 a1 = *(const float4*)&As[kk][ty4 + 64];
            const ulonglong2 b0 = *(const ulonglong2*)&Bs[kk][tx4];
            const ulonglong2 b1 = *(const ulonglong2*)&Bs[kk][tx4 + 64];

            u64 ap[8];
            ap[0] = dup2(a0.x); ap[1] = dup2(a0.y);
            ap[2] = dup2(a0.z); ap[3] = dup2(a0.w);
            ap[4] = dup2(a1.x); ap[5] = dup2(a1.y);
            ap[6] = dup2(a1.z); ap[7] = dup2(a1.w);
            const u64 bp[4] = { b0.x, b0.y, b1.x, b1.y };

#pragma unroll
            for (int i = 0; i < 8; i++)
#pragma unroll
                for (int j = 0; j < 4; j++)
                    acc2[i][j] = f2fma(ap[i], bp[j], acc2[i][j]);
        }
        __syncthreads();
    }

    // Epilogue: vectorized float4 stores
#pragma unroll
    for (int iq = 0; iq < 2; iq++) {
#pragma unroll
        for (int i = 0; i < 4; i++) {
            const int m  = row0 + iq * 64 + ty4 + i;
            const int ii = iq * 4 + i;
#pragma unroll
            for (int jq = 0; jq < 2; jq++) {
                const int n = col0 + jq * 64 + tx4;
                float r0, r1, r2, r3;
                upk2(acc2[ii][jq * 2 + 0], r0, r1);
                upk2(acc2[ii][jq * 2 + 1], r2, r3);
                const float4 bb = *(const float4*)&bias[n];
                float4 outv = make_float4((r0 + bb.x) * scale, (r1 + bb.y) * scale,
                                          (r2 + bb.z) * scale, (r3 + bb.w) * scale);
                if (split_mode) {
                    const int b = m >> 11, s = m & 2047;
                    const int h = n >> 6,  d = n & 63;
                    *(float4*)&C[(((size_t)(b * HEADS + h) * SS) + s) * HDIM + d] = outv;
                } else {
                    *(float4*)&C[(size_t)m * N + n] = outv;
                }
            }
        }
    }
}

// ---------------------------------------------------------------------------
// Flash attention, 64x64 tiles, swizzled smem, f32x2 math.
// smem: Q + K (reused for P) + V = 48KB static. Scale folded into Q.
// Mask: bool widened to 32-bit word per element; nonzero = keep.
// ---------------------------------------------------------------------------
__global__ __launch_bounds__(256) void flash_attn64(
    const float* __restrict__ Q, const float* __restrict__ Kg,
    const float* __restrict__ Vg, const unsigned int* __restrict__ mask,
    float* __restrict__ O)
{
    __shared__ float sQ[64 * 64];
    __shared__ float sK[64 * 64];   // reused as P after scores are consumed
    __shared__ float sV[64 * 64];

    const int tid = threadIdx.x;
    const int ty = tid >> 4;       // 0..15 -> 4 query rows
    const int tx = tid & 15;       // 0..15 -> 4 key cols / 4 d cols
    const int bh = blockIdx.y;
    const int b  = bh >> 4;
    const int h  = bh & 15;
    const int q0 = blockIdx.x * 64;

    const float* Qb = Q  + ((size_t)bh * SS + q0) * HDIM;
    const float* Kb = Kg + (size_t)bh * SS * HDIM;
    const float* Vb = Vg + (size_t)bh * SS * HDIM;

    // Load Q tile (swizzled)
#pragma unroll
    for (int i = 0; i < 4; i++) {
        const int j = tid + i * 256;
        *(float4*)&sQ[SW(j >> 4, j & 15)] = *(const float4*)&Qb[j * 4];
    }

    float m_i[4], l_i[4];
    u64 o2[4][2];
#pragma unroll
    for (int i = 0; i < 4; i++) {
        m_i[i] = -INFINITY;
        l_i[i] = 0.f;
        o2[i][0] = 0ull; o2[i][1] = 0ull;
    }

    for (int kb = 0; kb < 32; kb++) {
        __syncthreads();  // Q ready (iter 0); prior P/V reads done
        const float* Kt = Kb + (size_t)kb * 64 * HDIM;
        const float* Vt = Vb + (size_t)kb * 64 * HDIM;
#pragma unroll
        for (int i = 0; i < 4; i++) {
            const int j = tid + i * 256;
            const int dst = SW(j >> 4, j & 15);
            *(float4*)&sK[dst] = *(const float4*)&Kt[j * 4];
            *(float4*)&sV[dst] = *(const float4*)&Vt[j * 4];
        }
        __syncthreads();

        // Scores via f32x2 pair-accumulation over d
        u64 s2[4][4];
#pragma unroll
        for (int i = 0; i < 4; i++)
#pragma unroll
            for (int j = 0; j < 4; j++) s2[i][j] = 0ull;

#pragma unroll 4
        for (int d0 = 0; d0 < 16; d0++) {
            ulonglong2 qv[4], kv[4];
#pragma unroll
            for (int i = 0; i < 4; i++)
                qv[i] = *(const ulonglong2*)&sQ[SW(ty * 4 + i, d0)];
#pragma unroll
            for (int j = 0; j < 4; j++)
                kv[j] = *(const ulonglong2*)&sK[SW(tx * 4 + j, d0)];
#pragma unroll
            for (int i = 0; i < 4; i++)
#pragma unroll
                for (int j = 0; j < 4; j++) {
                    s2[i][j] = f2fma(qv[i].x, kv[j].x, s2[i][j]);
                    s2[i][j] = f2fma(qv[i].y, kv[j].y, s2[i][j]);
                }
        }

        float s[4][4];
#pragma unroll
        for (int i = 0; i < 4; i++)
#pragma unroll
            for (int j = 0; j < 4; j++) {
                float lo, hi; upk2(s2[i][j], lo, hi);
                s[i][j] = lo + hi;
            }

        // Mask: one 32-bit word per key; nonzero = keep.
        {
            const uint4 mk = *(const uint4*)&mask[(size_t)b * SS + kb * 64 + tx * 4];
            const float mb0 = mk.x ? 0.f : -1e30f;
            const float mb1 = mk.y ? 0.f : -1e30f;
            const float mb2 = mk.z ? 0.f : -1e30f;
            const float mb3 = mk.w ? 0.f : -1e30f;
#pragma unroll
            for (int i = 0; i < 4; i++) {
                s[i][0] += mb0; s[i][1] += mb1; s[i][2] += mb2; s[i][3] += mb3;
            }
        }

        // Online softmax per row (row spans 16 lanes of one half-warp)
#pragma unroll
        for (int i = 0; i < 4; i++) {
            float rm = fmaxf(fmaxf(s[i][0], s[i][1]), fmaxf(s[i][2], s[i][3]));
            rm = fmaxf(rm, __shfl_xor_sync(0xffffffffu, rm, 1));
            rm = fmaxf(rm, __shfl_xor_sync(0xffffffffu, rm, 2));
            rm = fmaxf(rm, __shfl_xor_sync(0xffffffffu, rm, 4));
            rm = fmaxf(rm, __shfl_xor_sync(0xffffffffu, rm, 8));
            const float nm = fmaxf(m_i[i], rm);
            const float corr = __expf(m_i[i] - nm);
            float rs = 0.f;
#pragma unroll
            for (int j = 0; j < 4; j++) {
                s[i][j] = __expf(s[i][j] - nm);
                rs += s[i][j];
            }
            rs += __shfl_xor_sync(0xffffffffu, rs, 1);
            rs += __shfl_xor_sync(0xffffffffu, rs, 2);
            rs += __shfl_xor_sync(0xffffffffu, rs, 4);
            rs += __shfl_xor_sync(0xffffffffu, rs, 8);
            l_i[i] = l_i[i] * corr + rs;
            m_i[i] = nm;
            const u64 cp = dup2(corr);
            o2[i][0] = f2mul(o2[i][0], cp);
            o2[i][1] = f2mul(o2[i][1], cp);
        }

        // Write P into the K tile (K fully consumed), swizzled
        __syncthreads();
#pragma unroll
        for (int i = 0; i < 4; i++)
            *(float4*)&sK[SW(ty * 4 + i, tx)] =
                make_float4(s[i][0], s[i][1], s[i][2], s[i][3]);
        __syncthreads();

        // PV: vectorized P loads (float4 over 4 keys), f32x2 accumulation
#pragma unroll 4
        for (int kc = 0; kc < 16; kc++) {
            float pvv[4][4];
#pragma unroll
            for (int i = 0; i < 4; i++)
                *(float4*)pvv[i] = *(const float4*)&sK[SW(ty * 4 + i, kc)];
            ulonglong2 vv[4];
#pragma unroll
            for (int jj = 0; jj < 4; jj++)
                vv[jj] = *(const ulonglong2*)&sV[SW(kc * 4 + jj, tx)];
#pragma unroll
            for (int jj = 0; jj < 4; jj++)
#pragma unroll
                for (int i = 0; i < 4; i++) {
                    const u64 p = dup2(pvv[i][jj]);
                    o2[i][0] = f2fma(p, vv[jj].x, o2[i][0]);
                    o2[i][1] = f2fma(p, vv[jj].y, o2[i][1]);
                }
        }
    }

    // Epilogue: normalize and write (B,S,E)
#pragma unroll
    for (int i = 0; i < 4; i++) {
        const float inv = 1.f / l_i[i];
        float o0, o1, o2f, o3;
        upk2(o2[i][0], o0, o1);
        upk2(o2[i][1], o2f, o3);
        const size_t row = (size_t)b * SS + q0 + ty * 4 + i;
        *(float4*)&O[row * EMB + h * HDIM + tx * 4] =
            make_float4(o0 * inv, o1 * inv, o2f * inv, o3 * inv);
    }
}

// ---------------------------------------------------------------------------
// Launch
// Inputs: query, key, value, mask, Wq, bq, Wk, bk, Wv, bv, Wo, bo
// ---------------------------------------------------------------------------
extern "C" void kernel_launch(void* const* d_in, const int* in_sizes, int n_in,
                              void* d_out, int out_size)
{
    const float* query = (const float*)d_in[0];
    const float* key   = (const float*)d_in[1];
    const float* value = (const float*)d_in[2];
    const unsigned int* mask = (const unsigned int*)d_in[3];
    const float* Wq = (const float*)d_in[4];
    const float* bq = (const float*)d_in[5];
    const float* Wk = (const float*)d_in[6];
    const float* bk = (const float*)d_in[7];
    const float* Wv = (const float*)d_in[8];
    const float* bv = (const float*)d_in[9];
    const float* Wo = (const float*)d_in[10];
    const float* bo = (const float*)d_in[11];
    float* out = (float*)d_out;

    float *q, *k, *v, *attn;
    cudaGetSymbolAddress((void**)&q,    g_q);
    cudaGetSymbolAddress((void**)&k,    g_k);
    cudaGetSymbolAddress((void**)&v,    g_v);
    cudaGetSymbolAddress((void**)&attn, g_attn);

    const dim3 blk(256);
    const dim3 gemm_grid(EMB / 128, MROWS / 128);   // (8, 64)
    const float qscale = 0.125f;                    // 1/sqrt(64)

    sgemm_bias<<<gemm_grid, blk>>>(query, Wq, bq, q, MROWS, EMB, EMB, qscale, 1);
    sgemm_bias<<<gemm_grid, blk>>>(key,   Wk, bk, k, MROWS, EMB, EMB, 1.0f,  1);
    sgemm_bias<<<gemm_grid, blk>>>(value, Wv, bv, v, MROWS, EMB, EMB, 1.0f,  1);

    flash_attn64<<<dim3(SS / 64, BB * HEADS), blk>>>(q, k, v, mask, attn);

    sgemm_bias<<<gemm_grid, blk>>>(attn, Wo, bo, out, MROWS, EMB, EMB, 1.0f, 0);
}

// round 11
// speedup vs baseline: 1.9420x; 1.0013x over previous
#include <cuda_runtime.h>
#include <cuda_bf16.h>
#include <math.h>

// Problem constants (fixed by setup_inputs)
#define BB 4
#define SS 2048
#define EMB 1024
#define HEADS 16
#define HDIM 64
#define MROWS (BB * SS)   // 8192

typedef unsigned long long u64;

// ---------------------------------------------------------------------------
// Packed f32x2 helpers (ptxas never auto-fuses; PTX-only path on sm_103a)
// ---------------------------------------------------------------------------
__device__ __forceinline__ u64 pk2(float lo, float hi) {
    u64 r; asm("mov.b64 %0, {%1, %2};" : "=l"(r) : "f"(lo), "f"(hi)); return r;
}
__device__ __forceinline__ u64 dup2(float v) {
    u64 r; asm("mov.b64 %0, {%1, %1};" : "=l"(r) : "f"(v)); return r;
}
__device__ __forceinline__ void upk2(u64 v, float& lo, float& hi) {
    asm("mov.b64 {%0, %1}, %2;" : "=f"(lo), "=f"(hi) : "l"(v));
}
__device__ __forceinline__ u64 f2fma(u64 a, u64 b, u64 c) {
    u64 d; asm("fma.rn.f32x2 %0, %1, %2, %3;" : "=l"(d) : "l"(a), "l"(b), "l"(c)); return d;
}
__device__ __forceinline__ u64 f2mul(u64 a, u64 b) {
    u64 d; asm("mul.rn.f32x2 %0, %1, %2;" : "=l"(d) : "l"(a), "l"(b)); return d;
}

// Swizzled float index for a [64 x 64] f32 tile: 16B chunk XOR'd by (row>>2).
// Kills the row-stride-64 same-bank pathology (16-way -> 2-way).
__device__ __forceinline__ int SW(int row, int chunk) {
    return (row << 6) + (((chunk ^ (row >> 2)) & 15) << 2);
}

// ---------------------------------------------------------------------------
// Scratch: __device__ globals (allocation APIs are forbidden).
// ---------------------------------------------------------------------------
__device__ float g_q[MROWS * EMB];
__device__ float g_k[MROWS * EMB];
__device__ float g_v[MROWS * EMB];
__device__ float g_attn[MROWS * EMB];

// ---------------------------------------------------------------------------
// SGEMM with bias: C = (A[MxK] @ W[KxN] + bias) * scale
// 128x128 tile, BK=8, 256 threads. 8x8 per-thread microtile computed as
// 8x4 f32x2 pair-accumulators. Columns split tx*4 / tx*4+64 (2-way LDS floor),
// rows ty*4 / ty*4+64. Register prefetch of the next A/B fragments.
// split_mode=1: write to (B,H,S,D) layout.
// ---------------------------------------------------------------------------
__global__ __launch_bounds__(256) void sgemm_bias(
    const float* __restrict__ A, const float* __restrict__ W,
    const float* __restrict__ bias, float* __restrict__ C,
    int M, int N, int K, float scale, int split_mode)
{
    __shared__ float As[8][128];
    __shared__ float Bs[8][128];

    const int tid = threadIdx.x;
    const int ty  = tid >> 4;          // 0..15
    const int tx  = tid & 15;          // 0..15
    const int row0 = blockIdx.y * 128;
    const int col0 = blockIdx.x * 128;
    const int ty4 = ty * 4, tx4 = tx * 4;

    u64 acc2[8][4];
#pragma unroll
    for (int i = 0; i < 8; i++)
#pragma unroll
        for (int j = 0; j < 4; j++) acc2[i][j] = 0ull;

    const int arow = tid >> 1;
    const int acol = (tid & 1) * 4;
    const int brow = tid >> 5;
    const int bcol = (tid & 31) * 4;

    const float* Ap = A + (size_t)(row0 + arow) * K + acol;
    const float* Bp = W + (size_t)brow * N + col0 + bcol;

    float4 av = *(const float4*)Ap;
    float4 bv = *(const float4*)Bp;

    for (int k0 = 0; k0 < K; k0 += 8) {
        As[acol + 0][arow] = av.x;
        As[acol + 1][arow] = av.y;
        As[acol + 2][arow] = av.z;
        As[acol + 3][arow] = av.w;
        *(float4*)&Bs[brow][bcol] = bv;
        __syncthreads();

        if (k0 + 8 < K) {       // prefetch next fragments under the compute
            Ap += 8;
            Bp += (size_t)8 * N;
            av = *(const float4*)Ap;
            bv = *(const float4*)Bp;
        }

#pragma unroll
        for (int kk = 0; kk < 8; kk++) {
            const float4 a0 = *(const float4*)&As[kk][ty4];
            const float4 a1 = *(const float4*)&As[kk][ty4 + 64];
            const ulonglong2 b0 = *(const ulonglong2*)&Bs[kk][tx4];
            const ulonglong2 b1 = *(const ulonglong2*)&Bs[kk][tx4 + 64];

            u64 ap[8];
            ap[0] = dup2(a0.x); ap[1] = dup2(a0.y);
            ap[2] = dup2(a0.z); ap[3] = dup2(a0.w);
            ap[4] = dup2(a1.x); ap[5] = dup2(a1.y);
            ap[6] = dup2(a1.z); ap[7] = dup2(a1.w);
            const u64 bp[4] = { b0.x, b0.y, b1.x, b1.y };

#pragma unroll
            for (int i = 0; i < 8; i++)
#pragma unroll
                for (int j = 0; j < 4; j++)
                    acc2[i][j] = f2fma(ap[i], bp[j], acc2[i][j]);
        }
        __syncthreads();
    }

    // Epilogue: vectorized float4 stores
#pragma unroll
    for (int iq = 0; iq < 2; iq++) {
#pragma unroll
        for (int i = 0; i < 4; i++) {
            const int m  = row0 + iq * 64 + ty4 + i;
            const int ii = iq * 4 + i;
#pragma unroll
            for (int jq = 0; jq < 2; jq++) {
                const int n = col0 + jq * 64 + tx4;
                float r0, r1, r2, r3;
                upk2(acc2[ii][jq * 2 + 0], r0, r1);
                upk2(acc2[ii][jq * 2 + 1], r2, r3);
                const float4 bb = *(const float4*)&bias[n];
                float4 outv = make_float4((r0 + bb.x) * scale, (r1 + bb.y) * scale,
                                          (r2 + bb.z) * scale, (r3 + bb.w) * scale);
                if (split_mode) {
                    const int b = m >> 11, s = m & 2047;
                    const int h = n >> 6,  d = n & 63;
                    *(float4*)&C[(((size_t)(b * HEADS + h) * SS) + s) * HDIM + d] = outv;
                } else {
                    *(float4*)&C[(size_t)m * N + n] = outv;
                }
            }
        }
    }
}

// ---------------------------------------------------------------------------
// Flash attention, 64x64 tiles, swizzled smem, f32x2 math.
// smem: Q + K (reused for P) + V = 48KB static. Scale folded into Q.
// Mask: bool widened to 32-bit word per element; nonzero = keep.
// ---------------------------------------------------------------------------
__global__ __launch_bounds__(256) void flash_attn64(
    const float* __restrict__ Q, const float* __restrict__ Kg,
    const float* __restrict__ Vg, const unsigned int* __restrict__ mask,
    float* __restrict__ O)
{
    __shared__ float sQ[64 * 64];
    __shared__ float sK[64 * 64];   // reused as P after scores are consumed
    __shared__ float sV[64 * 64];

    const int tid = threadIdx.x;
    const int ty = tid >> 4;       // 0..15 -> 4 query rows
    const int tx = tid & 15;       // 0..15 -> 4 key cols / 4 d cols
    const int bh = blockIdx.y;
    const int b  = bh >> 4;
    const int h  = bh & 15;
    const int q0 = blockIdx.x * 64;

    const float* Qb = Q  + ((size_t)bh * SS + q0) * HDIM;
    const float* Kb = Kg + (size_t)bh * SS * HDIM;
    const float* Vb = Vg + (size_t)bh * SS * HDIM;

    // Load Q tile (swizzled)
#pragma unroll
    for (int i = 0; i < 4; i++) {
        const int j = tid + i * 256;
        *(float4*)&sQ[SW(j >> 4, j & 15)] = *(const float4*)&Qb[j * 4];
    }

    float m_i[4], l_i[4];
    u64 o2[4][2];
#pragma unroll
    for (int i = 0; i < 4; i++) {
        m_i[i] = -INFINITY;
        l_i[i] = 0.f;
        o2[i][0] = 0ull; o2[i][1] = 0ull;
    }

    for (int kb = 0; kb < 32; kb++) {
        __syncthreads();  // Q ready (iter 0); prior P/V reads done
        const float* Kt = Kb + (size_t)kb * 64 * HDIM;
        const float* Vt = Vb + (size_t)kb * 64 * HDIM;
#pragma unroll
        for (int i = 0; i < 4; i++) {
            const int j = tid + i * 256;
            const int dst = SW(j >> 4, j & 15);
            *(float4*)&sK[dst] = *(const float4*)&Kt[j * 4];
            *(float4*)&sV[dst] = *(const float4*)&Vt[j * 4];
        }
        __syncthreads();

        // Scores via f32x2 pair-accumulation over d
        u64 s2[4][4];
#pragma unroll
        for (int i = 0; i < 4; i++)
#pragma unroll
            for (int j = 0; j < 4; j++) s2[i][j] = 0ull;

#pragma unroll 4
        for (int d0 = 0; d0 < 16; d0++) {
            ulonglong2 qv[4], kv[4];
#pragma unroll
            for (int i = 0; i < 4; i++)
                qv[i] = *(const ulonglong2*)&sQ[SW(ty * 4 + i, d0)];
#pragma unroll
            for (int j = 0; j < 4; j++)
                kv[j] = *(const ulonglong2*)&sK[SW(tx * 4 + j, d0)];
#pragma unroll
            for (int i = 0; i < 4; i++)
#pragma unroll
                for (int j = 0; j < 4; j++) {
                    s2[i][j] = f2fma(qv[i].x, kv[j].x, s2[i][j]);
                    s2[i][j] = f2fma(qv[i].y, kv[j].y, s2[i][j]);
                }
        }

        float s[4][4];
#pragma unroll
        for (int i = 0; i < 4; i++)
#pragma unroll
            for (int j = 0; j < 4; j++) {
                float lo, hi; upk2(s2[i][j], lo, hi);
                s[i][j] = lo + hi;
            }

        // Mask: one 32-bit word per key; nonzero = keep.
        {
            const uint4 mk = *(const uint4*)&mask[(size_t)b * SS + kb * 64 + tx * 4];
            const float mb0 = mk.x ? 0.f : -1e30f;
            const float mb1 = mk.y ? 0.f : -1e30f;
            const float mb2 = mk.z ? 0.f : -1e30f;
            const float mb3 = mk.w ? 0.f : -1e30f;
#pragma unroll
            for (int i = 0; i < 4; i++) {
                s[i][0] += mb0; s[i][1] += mb1; s[i][2] += mb2; s[i][3] += mb3;
            }
        }

        // Online softmax per row (row spans 16 lanes of one half-warp)
#pragma unroll
        for (int i = 0; i < 4; i++) {
            float rm = fmaxf(fmaxf(s[i][0], s[i][1]), fmaxf(s[i][2], s[i][3]));
            rm = fmaxf(rm, __shfl_xor_sync(0xffffffffu, rm, 1));
            rm = fmaxf(rm, __shfl_xor_sync(0xffffffffu, rm, 2));
            rm = fmaxf(rm, __shfl_xor_sync(0xffffffffu, rm, 4));
            rm = fmaxf(rm, __shfl_xor_sync(0xffffffffu, rm, 8));
            const float nm = fmaxf(m_i[i], rm);
            const float corr = __expf(m_i[i] - nm);
            float rs = 0.f;
#pragma unroll
            for (int j = 0; j < 4; j++) {
                s[i][j] = __expf(s[i][j] - nm);
                rs += s[i][j];
            }
            rs += __shfl_xor_sync(0xffffffffu, rs, 1);
            rs += __shfl_xor_sync(0xffffffffu, rs, 2);
            rs += __shfl_xor_sync(0xffffffffu, rs, 4);
            rs += __shfl_xor_sync(0xffffffffu, rs, 8);
            l_i[i] = l_i[i] * corr + rs;
            m_i[i] = nm;
            const u64 cp = dup2(corr);
            o2[i][0] = f2mul(o2[i][0], cp);
            o2[i][1] = f2mul(o2[i][1], cp);
        }

        // Write P into the K tile (K fully consumed), swizzled
        __syncthreads();
#pragma unroll
        for (int i = 0; i < 4; i++)
            *(float4*)&sK[SW(ty * 4 + i, tx)] =
                make_float4(s[i][0], s[i][1], s[i][2], s[i][3]);
        __syncthreads();

        // PV: vectorized P loads (float4 over 4 keys), f32x2 accumulation
#pragma unroll 4
        for (int kc = 0; kc < 16; kc++) {
            float pvv[4][4];
#pragma unroll
            for (int i = 0; i < 4; i++)
                *(float4*)pvv[i] = *(const float4*)&sK[SW(ty * 4 + i, kc)];
            ulonglong2 vv[4];
#pragma unroll
            for (int jj = 0; jj < 4; jj++)
                vv[jj] = *(const ulonglong2*)&sV[SW(kc * 4 + jj, tx)];
#pragma unroll
            for (int jj = 0; jj < 4; jj++)
#pragma unroll
                for (int i = 0; i < 4; i++) {
                    const u64 p = dup2(pvv[i][jj]);
                    o2[i][0] = f2fma(p, vv[jj].x, o2[i][0]);
                    o2[i][1] = f2fma(p, vv[jj].y, o2[i][1]);
                }
        }
    }

    // Epilogue: normalize and write (B,S,E)
#pragma unroll
    for (int i = 0; i < 4; i++) {
        const float inv = 1.f / l_i[i];
        float o0, o1, o2f, o3;
        upk2(o2[i][0], o0, o1);
        upk2(o2[i][1], o2f, o3);
        const size_t row = (size_t)b * SS + q0 + ty * 4 + i;
        *(float4*)&O[row * EMB + h * HDIM + tx * 4] =
            make_float4(o0 * inv, o1 * inv, o2f * inv, o3 * inv);
    }
}

// ---------------------------------------------------------------------------
// Launch
// Inputs: query, key, value, mask, Wq, bq, Wk, bk, Wv, bv, Wo, bo
// ---------------------------------------------------------------------------
extern "C" void kernel_launch(void* const* d_in, const int* in_sizes, int n_in,
                              void* d_out, int out_size)
{
    const float* query = (const float*)d_in[0];
    const float* key   = (const float*)d_in[1];
    const float* value = (const float*)d_in[2];
    const unsigned int* mask = (const unsigned int*)d_in[3];
    const float* Wq = (const float*)d_in[4];
    const float* bq = (const float*)d_in[5];
    const float* Wk = (const float*)d_in[6];
    const float* bk = (const float*)d_in[7];
    const float* Wv = (const float*)d_in[8];
    const float* bv = (const float*)d_in[9];
    const float* Wo = (const float*)d_in[10];
    const float* bo = (const float*)d_in[11];
    float* out = (float*)d_out;

    float *q, *k, *v, *attn;
    cudaGetSymbolAddress((void**)&q,    g_q);
    cudaGetSymbolAddress((void**)&k,    g_k);
    cudaGetSymbolAddress((void**)&v,    g_v);
    cudaGetSymbolAddress((void**)&attn, g_attn);

    const dim3 blk(256);
    const dim3 gemm_grid(EMB / 128, MROWS / 128);   // (8, 64)
    const float qscale = 0.125f;                    // 1/sqrt(64)

    sgemm_bias<<<gemm_grid, blk>>>(query, Wq, bq, q, MROWS, EMB, EMB, qscale, 1);
    sgemm_bias<<<gemm_grid, blk>>>(key,   Wk, bk, k, MROWS, EMB, EMB, 1.0f,  1);
    sgemm_bias<<<gemm_grid, blk>>>(value, Wv, bv, v, MROWS, EMB, EMB, 1.0f,  1);

    flash_attn64<<<dim3(SS / 64, BB * HEADS), blk>>>(q, k, v, mask, attn);

    sgemm_bias<<<gemm_grid, blk>>>(attn, Wo, bo, out, MROWS, EMB, EMB, 1.0f, 0);
}

// round 12
// speedup vs baseline: 1.9421x; 1.0000x over previous
#include <cuda_runtime.h>
#include <cuda_bf16.h>
#include <math.h>

// Problem constants (fixed by setup_inputs)
#define BB 4
#define SS 2048
#define EMB 1024
#define HEADS 16
#define HDIM 64
#define MROWS (BB * SS)   // 8192

typedef unsigned long long u64;

// ---------------------------------------------------------------------------
// Packed f32x2 helpers (ptxas never auto-fuses; PTX-only path on sm_103a)
// ---------------------------------------------------------------------------
__device__ __forceinline__ u64 pk2(float lo, float hi) {
    u64 r; asm("mov.b64 %0, {%1, %2};" : "=l"(r) : "f"(lo), "f"(hi)); return r;
}
__device__ __forceinline__ u64 dup2(float v) {
    u64 r; asm("mov.b64 %0, {%1, %1};" : "=l"(r) : "f"(v)); return r;
}
__device__ __forceinline__ void upk2(u64 v, float& lo, float& hi) {
    asm("mov.b64 {%0, %1}, %2;" : "=f"(lo), "=f"(hi) : "l"(v));
}
__device__ __forceinline__ u64 f2fma(u64 a, u64 b, u64 c) {
    u64 d; asm("fma.rn.f32x2 %0, %1, %2, %3;" : "=l"(d) : "l"(a), "l"(b), "l"(c)); return d;
}
__device__ __forceinline__ u64 f2mul(u64 a, u64 b) {
    u64 d; asm("mul.rn.f32x2 %0, %1, %2;" : "=l"(d) : "l"(a), "l"(b)); return d;
}

// Swizzled float index for a [64 x 64] f32 tile: 16B chunk XOR'd by (row>>2).
// Kills the row-stride-64 same-bank pathology (16-way -> 2-way).
__device__ __forceinline__ int SW(int row, int chunk) {
    return (row << 6) + (((chunk ^ (row >> 2)) & 15) << 2);
}

// ---------------------------------------------------------------------------
// Scratch: __device__ globals (allocation APIs are forbidden).
// ---------------------------------------------------------------------------
__device__ float g_q[MROWS * EMB];
__device__ float g_k[MROWS * EMB];
__device__ float g_v[MROWS * EMB];
__device__ float g_attn[MROWS * EMB];

// ---------------------------------------------------------------------------
// SGEMM with bias: C = (A[MxK] @ W[KxN] + bias) * scale
// 128x128 tile, BK=8, 256 threads. 8x8 per-thread microtile computed as
// 8x4 f32x2 pair-accumulators. Columns split tx*4 / tx*4+64 (2-way LDS floor),
// rows ty*4 / ty*4+64. Register prefetch of the next A/B fragments.
// split_mode=1: write to (B,H,S,D) layout.
// ---------------------------------------------------------------------------
__global__ __launch_bounds__(256) void sgemm_bias(
    const float* __restrict__ A, const float* __restrict__ W,
    const float* __restrict__ bias, float* __restrict__ C,
    int M, int N, int K, float scale, int split_mode)
{
    __shared__ float As[8][128];
    __shared__ float Bs[8][128];

    const int tid = threadIdx.x;
    const int ty  = tid >> 4;          // 0..15
    const int tx  = tid & 15;          // 0..15
    const int row0 = blockIdx.y * 128;
    const int col0 = blockIdx.x * 128;
    const int ty4 = ty * 4, tx4 = tx * 4;

    u64 acc2[8][4];
#pragma unroll
    for (int i = 0; i < 8; i++)
#pragma unroll
        for (int j = 0; j < 4; j++) acc2[i][j] = 0ull;

    const int arow = tid >> 1;
    const int acol = (tid & 1) * 4;
    const int brow = tid >> 5;
    const int bcol = (tid & 31) * 4;

    const float* Ap = A + (size_t)(row0 + arow) * K + acol;
    const float* Bp = W + (size_t)brow * N + col0 + bcol;

    float4 av = *(const float4*)Ap;
    float4 bv = *(const float4*)Bp;

    for (int k0 = 0; k0 < K; k0 += 8) {
        As[acol + 0][arow] = av.x;
        As[acol + 1][arow] = av.y;
        As[acol + 2][arow] = av.z;
        As[acol + 3][arow] = av.w;
        *(float4*)&Bs[brow][bcol] = bv;
        __syncthreads();

        if (k0 + 8 < K) {       // prefetch next fragments under the compute
            Ap += 8;
            Bp += (size_t)8 * N;
            av = *(const float4*)Ap;
            bv = *(const float4*)Bp;
        }

#pragma unroll
        for (int kk = 0; kk < 8; kk++) {
            const float4 a0 = *(const float4*)&As[kk][ty4];
            const float4 a1 = *(const float4*)&As[kk][ty4 + 64];
            const ulonglong2 b0 = *(const ulonglong2*)&Bs[kk][tx4];
            const ulonglong2 b1 = *(const ulonglong2*)&Bs[kk][tx4 + 64];

            u64 ap[8];
            ap[0] = dup2(a0.x); ap[1] = dup2(a0.y);
            ap[2] = dup2(a0.z); ap[3] = dup2(a0.w);
            ap[4] = dup2(a1.x); ap[5] = dup2(a1.y);
            ap[6] = dup2(a1.z); ap[7] = dup2(a1.w);
            const u64 bp[4] = { b0.x, b0.y, b1.x, b1.y };

#pragma unroll
            for (int i = 0; i < 8; i++)
#pragma unroll
                for (int j = 0; j < 4; j++)
                    acc2[i][j] = f2fma(ap[i], bp[j], acc2[i][j]);
        }
        __syncthreads();
    }

    // Epilogue: vectorized float4 stores
#pragma unroll
    for (int iq = 0; iq < 2; iq++) {
#pragma unroll
        for (int i = 0; i < 4; i++) {
            const int m  = row0 + iq * 64 + ty4 + i;
            const int ii = iq * 4 + i;
#pragma unroll
            for (int jq = 0; jq < 2; jq++) {
                const int n = col0 + jq * 64 + tx4;
                float r0, r1, r2, r3;
                upk2(acc2[ii][jq * 2 + 0], r0, r1);
                upk2(acc2[ii][jq * 2 + 1], r2, r3);
                const float4 bb = *(const float4*)&bias[n];
                float4 outv = make_float4((r0 + bb.x) * scale, (r1 + bb.y) * scale,
                                          (r2 + bb.z) * scale, (r3 + bb.w) * scale);
                if (split_mode) {
                    const int b = m >> 11, s = m & 2047;
                    const int h = n >> 6,  d = n & 63;
                    *(float4*)&C[(((size_t)(b * HEADS + h) * SS) + s) * HDIM + d] = outv;
                } else {
                    *(float4*)&C[(size_t)m * N + n] = outv;
                }
            }
        }
    }
}

// ---------------------------------------------------------------------------
// Flash attention, 64x64 tiles, swizzled smem, f32x2 math.
// smem: Q + K (reused for P) + V = 48KB static. Scale folded into Q.
// Mask: bool widened to 32-bit word per element; nonzero = keep.
// ---------------------------------------------------------------------------
__global__ __launch_bounds__(256) void flash_attn64(
    const float* __restrict__ Q, const float* __restrict__ Kg,
    const float* __restrict__ Vg, const unsigned int* __restrict__ mask,
    float* __restrict__ O)
{
    __shared__ float sQ[64 * 64];
    __shared__ float sK[64 * 64];   // reused as P after scores are consumed
    __shared__ float sV[64 * 64];

    const int tid = threadIdx.x;
    const int ty = tid >> 4;       // 0..15 -> 4 query rows
    const int tx = tid & 15;       // 0..15 -> 4 key cols / 4 d cols
    const int bh = blockIdx.y;
    const int b  = bh >> 4;
    const int h  = bh & 15;
    const int q0 = blockIdx.x * 64;

    const float* Qb = Q  + ((size_t)bh * SS + q0) * HDIM;
    const float* Kb = Kg + (size_t)bh * SS * HDIM;
    const float* Vb = Vg + (size_t)bh * SS * HDIM;

    // Load Q tile (swizzled)
#pragma unroll
    for (int i = 0; i < 4; i++) {
        const int j = tid + i * 256;
        *(float4*)&sQ[SW(j >> 4, j & 15)] = *(const float4*)&Qb[j * 4];
    }

    float m_i[4], l_i[4];
    u64 o2[4][2];
#pragma unroll
    for (int i = 0; i < 4; i++) {
        m_i[i] = -INFINITY;
        l_i[i] = 0.f;
        o2[i][0] = 0ull; o2[i][1] = 0ull;
    }

    for (int kb = 0; kb < 32; kb++) {
        __syncthreads();  // Q ready (iter 0); prior P/V reads done
        const float* Kt = Kb + (size_t)kb * 64 * HDIM;
        const float* Vt = Vb + (size_t)kb * 64 * HDIM;
#pragma unroll
        for (int i = 0; i < 4; i++) {
            const int j = tid + i * 256;
            const int dst = SW(j >> 4, j & 15);
            *(float4*)&sK[dst] = *(const float4*)&Kt[j * 4];
            *(float4*)&sV[dst] = *(const float4*)&Vt[j * 4];
        }
        __syncthreads();

        // Scores via f32x2 pair-accumulation over d
        u64 s2[4][4];
#pragma unroll
        for (int i = 0; i < 4; i++)
#pragma unroll
            for (int j = 0; j < 4; j++) s2[i][j] = 0ull;

#pragma unroll 4
        for (int d0 = 0; d0 < 16; d0++) {
            ulonglong2 qv[4], kv[4];
#pragma unroll
            for (int i = 0; i < 4; i++)
                qv[i] = *(const ulonglong2*)&sQ[SW(ty * 4 + i, d0)];
#pragma unroll
            for (int j = 0; j < 4; j++)
                kv[j] = *(const ulonglong2*)&sK[SW(tx * 4 + j, d0)];
#pragma unroll
            for (int i = 0; i < 4; i++)
#pragma unroll
                for (int j = 0; j < 4; j++) {
                    s2[i][j] = f2fma(qv[i].x, kv[j].x, s2[i][j]);
                    s2[i][j] = f2fma(qv[i].y, kv[j].y, s2[i][j]);
                }
        }

        float s[4][4];
#pragma unroll
        for (int i = 0; i < 4; i++)
#pragma unroll
            for (int j = 0; j < 4; j++) {
                float lo, hi; upk2(s2[i][j], lo, hi);
                s[i][j] = lo + hi;
            }

        // Mask: one 32-bit word per key; nonzero = keep.
        {
            const uint4 mk = *(const uint4*)&mask[(size_t)b * SS + kb * 64 + tx * 4];
            const float mb0 = mk.x ? 0.f : -1e30f;
            const float mb1 = mk.y ? 0.f : -1e30f;
            const float mb2 = mk.z ? 0.f : -1e30f;
            const float mb3 = mk.w ? 0.f : -1e30f;
#pragma unroll
            for (int i = 0; i < 4; i++) {
                s[i][0] += mb0; s[i][1] += mb1; s[i][2] += mb2; s[i][3] += mb3;
            }
        }

        // Online softmax per row (row spans 16 lanes of one half-warp)
#pragma unroll
        for (int i = 0; i < 4; i++) {
            float rm = fmaxf(fmaxf(s[i][0], s[i][1]), fmaxf(s[i][2], s[i][3]));
            rm = fmaxf(rm, __shfl_xor_sync(0xffffffffu, rm, 1));
            rm = fmaxf(rm, __shfl_xor_sync(0xffffffffu, rm, 2));
            rm = fmaxf(rm, __shfl_xor_sync(0xffffffffu, rm, 4));
            rm = fmaxf(rm, __shfl_xor_sync(0xffffffffu, rm, 8));
            const float nm = fmaxf(m_i[i], rm);
            const float corr = __expf(m_i[i] - nm);
            float rs = 0.f;
#pragma unroll
            for (int j = 0; j < 4; j++) {
                s[i][j] = __expf(s[i][j] - nm);
                rs += s[i][j];
            }
            rs += __shfl_xor_sync(0xffffffffu, rs, 1);
            rs += __shfl_xor_sync(0xffffffffu, rs, 2);
            rs += __shfl_xor_sync(0xffffffffu, rs, 4);
            rs += __shfl_xor_sync(0xffffffffu, rs, 8);
            l_i[i] = l_i[i] * corr + rs;
            m_i[i] = nm;
            const u64 cp = dup2(corr);
            o2[i][0] = f2mul(o2[i][0], cp);
            o2[i][1] = f2mul(o2[i][1], cp);
        }

        // Write P into the K tile (K fully consumed), swizzled
        __syncthreads();
#pragma unroll
        for (int i = 0; i < 4; i++)
            *(float4*)&sK[SW(ty * 4 + i, tx)] =
                make_float4(s[i][0], s[i][1], s[i][2], s[i][3]);
        __syncthreads();

        // PV: vectorized P loads (float4 over 4 keys), f32x2 accumulation
#pragma unroll 4
        for (int kc = 0; kc < 16; kc++) {
            float pvv[4][4];
#pragma unroll
            for (int i = 0; i < 4; i++)
                *(float4*)pvv[i] = *(const float4*)&sK[SW(ty * 4 + i, kc)];
            ulonglong2 vv[4];
#pragma unroll
            for (int jj = 0; jj < 4; jj++)
                vv[jj] = *(const ulonglong2*)&sV[SW(kc * 4 + jj, tx)];
#pragma unroll
            for (int jj = 0; jj < 4; jj++)
#pragma unroll
                for (int i = 0; i < 4; i++) {
                    const u64 p = dup2(pvv[i][jj]);
                    o2[i][0] = f2fma(p, vv[jj].x, o2[i][0]);
                    o2[i][1] = f2fma(p, vv[jj].y, o2[i][1]);
                }
        }
    }

    // Epilogue: normalize and write (B,S,E)
#pragma unroll
    for (int i = 0; i < 4; i++) {
        const float inv = 1.f / l_i[i];
        float o0, o1, o2f, o3;
        upk2(o2[i][0], o0, o1);
        upk2(o2[i][1], o2f, o3);
        const size_t row = (size_t)b * SS + q0 + ty * 4 + i;
        *(float4*)&O[row * EMB + h * HDIM + tx * 4] =
            make_float4(o0 * inv, o1 * inv, o2f * inv, o3 * inv);
    }
}

// ---------------------------------------------------------------------------
// Launch
// Inputs: query, key, value, mask, Wq, bq, Wk, bk, Wv, bv, Wo, bo
// ---------------------------------------------------------------------------
extern "C" void kernel_launch(void* const* d_in, const int* in_sizes, int n_in,
                              void* d_out, int out_size)
{
    const float* query = (const float*)d_in[0];
    const float* key   = (const float*)d_in[1];
    const float* value = (const float*)d_in[2];
    const unsigned int* mask = (const unsigned int*)d_in[3];
    const float* Wq = (const float*)d_in[4];
    const float* bq = (const float*)d_in[5];
    const float* Wk = (const float*)d_in[6];
    const float* bk = (const float*)d_in[7];
    const float* Wv = (const float*)d_in[8];
    const float* bv = (const float*)d_in[9];
    const float* Wo = (const float*)d_in[10];
    const float* bo = (const float*)d_in[11];
    float* out = (float*)d_out;

    float *q, *k, *v, *attn;
    cudaGetSymbolAddress((void**)&q,    g_q);
    cudaGetSymbolAddress((void**)&k,    g_k);
    cudaGetSymbolAddress((void**)&v,    g_v);
    cudaGetSymbolAddress((void**)&attn, g_attn);

    const dim3 blk(256);
    const dim3 gemm_grid(EMB / 128, MROWS / 128);   // (8, 64)
    const float qscale = 0.125f;                    // 1/sqrt(64)

    sgemm_bias<<<gemm_grid, blk>>>(query, Wq, bq, q, MROWS, EMB, EMB, qscale, 1);
    sgemm_bias<<<gemm_grid, blk>>>(key,   Wk, bk, k, MROWS, EMB, EMB, 1.0f,  1);
    sgemm_bias<<<gemm_grid, blk>>>(value, Wv, bv, v, MROWS, EMB, EMB, 1.0f,  1);

    flash_attn64<<<dim3(SS / 64, BB * HEADS), blk>>>(q, k, v, mask, attn);

    sgemm_bias<<<gemm_grid, blk>>>(attn, Wo, bo, out, MROWS, EMB, EMB, 1.0f, 0);
}

// round 14
// speedup vs baseline: 2.5268x; 1.3011x over previous
#include <cuda_runtime.h>
#include <cuda_bf16.h>
#include <math.h>

#define BB 4
#define SS 2048
#define EMB 1024
#define HEADS 16
#define HDIM 64
#define MROWS (BB * SS)   // 8192

typedef unsigned long long u64;
typedef unsigned int u32;

// ---------------- f32x2 helpers (flash) ----------------
__device__ __forceinline__ u64 dup2(float v) {
    u64 r; asm("mov.b64 %0, {%1, %1};" : "=l"(r) : "f"(v)); return r;
}
__device__ __forceinline__ void upk2(u64 v, float& lo, float& hi) {
    asm("mov.b64 {%0, %1}, %2;" : "=f"(lo), "=f"(hi) : "l"(v));
}
__device__ __forceinline__ u64 f2fma(u64 a, u64 b, u64 c) {
    u64 d; asm("fma.rn.f32x2 %0, %1, %2, %3;" : "=l"(d) : "l"(a), "l"(b), "l"(c)); return d;
}
__device__ __forceinline__ u64 f2mul(u64 a, u64 b) {
    u64 d; asm("mul.rn.f32x2 %0, %1, %2;" : "=l"(d) : "l"(a), "l"(b)); return d;
}
__device__ __forceinline__ int SWF(int row, int chunk) {  // [64x64] f32 tile swizzle
    return (row << 6) + (((chunk ^ (row >> 2)) & 15) << 2);
}
#define SWZ(o) ((o) ^ (((o) >> 3) & 0x70))               // SW128 byte swizzle

// ---------------- baseline (non-'a') async + mma helpers ----------------
__device__ __forceinline__ u32 smem_u32(const void* p) {
    u32 a; asm("{ .reg .u64 t; cvta.to.shared.u64 t, %1; cvt.u32.u64 %0, t; }" : "=r"(a) : "l"(p));
    return a;
}
__device__ __forceinline__ void cp16(u32 dst, const void* src) {
    asm volatile("cp.async.cg.shared.global [%0], [%1], 16;" :: "r"(dst), "l"(src) : "memory");
}
__device__ __forceinline__ void cp_commit() { asm volatile("cp.async.commit_group;" ::: "memory"); }
__device__ __forceinline__ void cp_wait1()  { asm volatile("cp.async.wait_group 1;"  ::: "memory"); }
__device__ __forceinline__ void cp_wait0()  { asm volatile("cp.async.wait_group 0;"  ::: "memory"); }

__device__ __forceinline__ void ldm_x4(u32* r, u32 addr) {
    asm volatile("ldmatrix.sync.aligned.m8n8.x4.shared.b16 {%0,%1,%2,%3}, [%4];"
        : "=r"(r[0]), "=r"(r[1]), "=r"(r[2]), "=r"(r[3]) : "r"(addr));
}
__device__ __forceinline__ void ldm_x2(u32* r, u32 addr) {
    asm volatile("ldmatrix.sync.aligned.m8n8.x2.shared.b16 {%0,%1}, [%2];"
        : "=r"(r[0]), "=r"(r[1]) : "r"(addr));
}
__device__ __forceinline__ void mma_bf16(float* c, const u32* a, const u32* b) {
    asm volatile(
        "mma.sync.aligned.m16n8k16.row.col.f32.bf16.bf16.f32 "
        "{%0,%1,%2,%3}, {%4,%5,%6,%7}, {%8,%9}, {%0,%1,%2,%3};"
        : "+f"(c[0]), "+f"(c[1]), "+f"(c[2]), "+f"(c[3])
        : "r"(a[0]), "r"(a[1]), "r"(a[2]), "r"(a[3]), "r"(b[0]), "r"(b[1]));
}

// ---------------- scratch ----------------
__device__ float g_q[MROWS * EMB];
__device__ float g_k[MROWS * EMB];
__device__ float g_v[MROWS * EMB];
__device__ float g_attn[MROWS * EMB];
__device__ __nv_bfloat16 g_ahi[MROWS * EMB];
__device__ __nv_bfloat16 g_alo[MROWS * EMB];
__device__ __nv_bfloat16 g_wthi[EMB * EMB];
__device__ __nv_bfloat16 g_wtlo[EMB * EMB];

// ---------------- bf16 split prep ----------------
__device__ __forceinline__ unsigned short bfbits(float x) {
    __nv_bfloat16 h = __float2bfloat16(x);
    return reinterpret_cast<unsigned short&>(h);
}
__device__ __forceinline__ float bfval(unsigned short b) {
    __nv_bfloat16 h = reinterpret_cast<__nv_bfloat16&>(b);
    return __bfloat162float(h);
}

__global__ __launch_bounds__(256) void split_bf16(
    const float* __restrict__ x, __nv_bfloat16* __restrict__ hi,
    __nv_bfloat16* __restrict__ lo, int n4)
{
    int i = blockIdx.x * blockDim.x + threadIdx.x;
    const int stride = gridDim.x * blockDim.x;
    for (; i < n4; i += stride) {
        const float4 v = ((const float4*)x)[i];
        unsigned short h0 = bfbits(v.x), h1 = bfbits(v.y), h2 = bfbits(v.z), h3 = bfbits(v.w);
        unsigned short l0 = bfbits(v.x - bfval(h0)), l1 = bfbits(v.y - bfval(h1));
        unsigned short l2 = bfbits(v.z - bfval(h2)), l3 = bfbits(v.w - bfval(h3));
        ((uint2*)hi)[i] = make_uint2((u32)h0 | ((u32)h1 << 16), (u32)h2 | ((u32)h3 << 16));
        ((uint2*)lo)[i] = make_uint2((u32)l0 | ((u32)l1 << 16), (u32)l2 | ((u32)l3 << 16));
    }
}

// W[K][N] -> Wt hi/lo [N][K]
__global__ void transpose_split(
    const float* __restrict__ W, __nv_bfloat16* __restrict__ hi,
    __nv_bfloat16* __restrict__ lo)
{
    __shared__ float t[32][33];
    const int k0 = blockIdx.y * 32, n0 = blockIdx.x * 32;
    const int x = threadIdx.x, y0 = threadIdx.y;   // block (32,8)
#pragma unroll
    for (int i = 0; i < 4; i++) {
        const int y = y0 + i * 8;
        t[y][x] = W[(size_t)(k0 + y) * EMB + n0 + x];
    }
    __syncthreads();
#pragma unroll
    for (int i = 0; i < 4; i++) {
        const int nn = y0 + i * 8;
        const float v = t[x][nn];                  // = W[k0+x][n0+nn]
        const unsigned short h = bfbits(v);
        const unsigned short l = bfbits(v - bfval(h));
        hi[(size_t)(n0 + nn) * EMB + k0 + x] = reinterpret_cast<const __nv_bfloat16&>(h);
        lo[(size_t)(n0 + nn) * EMB + k0 + x] = reinterpret_cast<const __nv_bfloat16&>(l);
    }
}

// ---------------- mma.sync GEMM (bf16x3) ----------------
// C[m][n] = (sum_k A[m][k]*W[k][n] + bias[n]) * scale with A hi/lo [M][K] and
// Wt hi/lo [N][K] (K-major bf16). CTA 128x128, BK=64, double buffered.
// 8 warps 2(m) x 4(n); warp tile 64x32 = 4x4 of m16n8k16. 3 passes: hh, hl, lh.
#define GEMM_NIT 16
#define STAGE_BYTES 65536        // 4 x 16KB (Ahi, Alo, Bhi, Blo)
#define GEMM_SMEM (2 * STAGE_BYTES)

__device__ __forceinline__ void gemm_load_stage(
    u32 st, const __nv_bfloat16* __restrict__ Ahi, const __nv_bfloat16* __restrict__ Alo,
    const __nv_bfloat16* __restrict__ Bhi, const __nv_bfloat16* __restrict__ Blo,
    int m0, int n0, int k0, int tid)
{
#pragma unroll
    for (int i = 0; i < 4; i++) {
        const int c = tid + i * 256;                 // 0..1023
        const int row = c >> 3, col16 = c & 7;
        const u32 sw = (u32)SWZ(row * 128 + col16 * 16);
        const size_t ga = (size_t)(m0 + row) * EMB + k0 + col16 * 8;
        const size_t gb = (size_t)(n0 + row) * EMB + k0 + col16 * 8;
        cp16(st +     0 + sw, Ahi + ga);
        cp16(st + 16384 + sw, Alo + ga);
        cp16(st + 32768 + sw, Bhi + gb);
        cp16(st + 49152 + sw, Blo + gb);
    }
}

__global__ __launch_bounds__(256)
void gemm_mma(const __nv_bfloat16* __restrict__ Ahi, const __nv_bfloat16* __restrict__ Alo,
              const __nv_bfloat16* __restrict__ Bhi, const __nv_bfloat16* __restrict__ Blo,
              const float* __restrict__ bias, float* __restrict__ C,
              float scale, int split_mode)
{
    extern __shared__ __align__(1024) char smem[];
    const u32 sb = smem_u32(smem);
    const int tid  = threadIdx.x;
    const int lane = tid & 31, wid = tid >> 5;
    const int wm = wid & 1, wn = wid >> 1;           // 2 x 4 warp grid
    const int m0 = blockIdx.y * 128, n0 = blockIdx.x * 128;

    float acc[4][4][4];
#pragma unroll
    for (int mt = 0; mt < 4; mt++)
#pragma unroll
        for (int nt = 0; nt < 4; nt++)
#pragma unroll
            for (int e = 0; e < 4; e++) acc[mt][nt][e] = 0.f;

    // ldmatrix per-lane base offsets within a 128x128B tile
    const int a_row = (lane & 15);                   // + mt*16 + wm*64
    const int a_kb  = (lane >> 4) * 16;              // + ks*32
    const int b_row = (lane & 7);                    // + nt*8 + wn*32
    const int b_kb  = ((lane >> 3) & 1) * 16;        // + ks*32

    gemm_load_stage(sb,               Ahi, Alo, Bhi, Blo, m0, n0, 0,  tid); cp_commit();
    gemm_load_stage(sb + STAGE_BYTES, Ahi, Alo, Bhi, Blo, m0, n0, 64, tid); cp_commit();

    for (int it = 0; it < GEMM_NIT; it++) {
        const u32 stg = sb + (it & 1) * STAGE_BYTES;
        if (it >= GEMM_NIT - 2) cp_wait0(); else cp_wait1();
        __syncthreads();

        const u32 sAh = stg, sAl = stg + 16384, sBh = stg + 32768, sBl = stg + 49152;
#pragma unroll
        for (int ks = 0; ks < 4; ks++) {
            u32 ah[4][4], al[4][4], bh[4][2], bl[4][2];
#pragma unroll
            for (int mt = 0; mt < 4; mt++) {
                const int r = wm * 64 + mt * 16 + a_row;
                const u32 off = (u32)SWZ(r * 128 + ks * 32 + a_kb);
                ldm_x4(ah[mt], sAh + off);
                ldm_x4(al[mt], sAl + off);
            }
#pragma unroll
            for (int nt = 0; nt < 4; nt++) {
                const int r = wn * 32 + nt * 8 + b_row;
                const u32 off = (u32)SWZ(r * 128 + ks * 32 + b_kb);
                ldm_x2(bh[nt], sBh + off);
                ldm_x2(bl[nt], sBl + off);
            }
#pragma unroll
            for (int mt = 0; mt < 4; mt++)
#pragma unroll
                for (int nt = 0; nt < 4; nt++) {
                    mma_bf16(acc[mt][nt], ah[mt], bh[nt]);
                    mma_bf16(acc[mt][nt], ah[mt], bl[nt]);
                    mma_bf16(acc[mt][nt], al[mt], bh[nt]);
                }
        }
        __syncthreads();
        if (it + 2 < GEMM_NIT) {
            gemm_load_stage(stg, Ahi, Alo, Bhi, Blo, m0, n0, (it + 2) * 64, tid);
            cp_commit();
        }
    }

    // Epilogue: c0,c1 at (row, col..col+1); c2,c3 at (row+8, col..col+1)
#pragma unroll
    for (int mt = 0; mt < 4; mt++) {
        const int r0 = m0 + wm * 64 + mt * 16 + (lane >> 2);
#pragma unroll
        for (int nt = 0; nt < 4; nt++) {
            const int cc = n0 + wn * 32 + nt * 8 + (lane & 3) * 2;
            const float2 bb = *(const float2*)&bias[cc];
#pragma unroll
            for (int half = 0; half < 2; half++) {
                const int m = r0 + half * 8;
                const float2 ov = make_float2(
                    (acc[mt][nt][half * 2 + 0] + bb.x) * scale,
                    (acc[mt][nt][half * 2 + 1] + bb.y) * scale);
                if (split_mode) {
                    const int b = m >> 11, s2 = m & 2047;
                    const int h = cc >> 6, dd = cc & 63;
                    *(float2*)&C[(((size_t)(b * HEADS + h) * SS) + s2) * HDIM + dd] = ov;
                } else {
                    *(float2*)&C[(size_t)m * EMB + cc] = ov;
                }
            }
        }
    }
}

// ---------------- flash attention (unchanged from passing round) ----------------
__global__ __launch_bounds__(256) void flash_attn64(
    const float* __restrict__ Q, const float* __restrict__ Kg,
    const float* __restrict__ Vg, const unsigned int* __restrict__ mask,
    float* __restrict__ O)
{
    __shared__ float sQ[64 * 64];
    __shared__ float sK[64 * 64];
    __shared__ float sV[64 * 64];

    const int tid = threadIdx.x;
    const int ty = tid >> 4, tx = tid & 15;
    const int bh = blockIdx.y;
    const int b = bh >> 4, h = bh & 15;
    const int q0 = blockIdx.x * 64;

    const float* Qb = Q  + ((size_t)bh * SS + q0) * HDIM;
    const float* Kb = Kg + (size_t)bh * SS * HDIM;
    const float* Vb = Vg + (size_t)bh * SS * HDIM;

#pragma unroll
    for (int i = 0; i < 4; i++) {
        const int j = tid + i * 256;
        *(float4*)&sQ[SWF(j >> 4, j & 15)] = *(const float4*)&Qb[j * 4];
    }

    float m_i[4], l_i[4];
    u64 o2[4][2];
#pragma unroll
    for (int i = 0; i < 4; i++) {
        m_i[i] = -INFINITY; l_i[i] = 0.f; o2[i][0] = 0ull; o2[i][1] = 0ull;
    }

    for (int kb = 0; kb < 32; kb++) {
        __syncthreads();
        const float* Kt = Kb + (size_t)kb * 64 * HDIM;
        const float* Vt = Vb + (size_t)kb * 64 * HDIM;
#pragma unroll
        for (int i = 0; i < 4; i++) {
            const int j = tid + i * 256;
            const int dst = SWF(j >> 4, j & 15);
            *(float4*)&sK[dst] = *(const float4*)&Kt[j * 4];
            *(float4*)&sV[dst] = *(const float4*)&Vt[j * 4];
        }
        __syncthreads();

        u64 s2[4][4];
#pragma unroll
        for (int i = 0; i < 4; i++)
#pragma unroll
            for (int j = 0; j < 4; j++) s2[i][j] = 0ull;

#pragma unroll 4
        for (int d0 = 0; d0 < 16; d0++) {
            ulonglong2 qv[4], kv[4];
#pragma unroll
            for (int i = 0; i < 4; i++) qv[i] = *(const ulonglong2*)&sQ[SWF(ty * 4 + i, d0)];
#pragma unroll
            for (int j = 0; j < 4; j++) kv[j] = *(const ulonglong2*)&sK[SWF(tx * 4 + j, d0)];
#pragma unroll
            for (int i = 0; i < 4; i++)
#pragma unroll
                for (int j = 0; j < 4; j++) {
                    s2[i][j] = f2fma(qv[i].x, kv[j].x, s2[i][j]);
                    s2[i][j] = f2fma(qv[i].y, kv[j].y, s2[i][j]);
                }
        }

        float s[4][4];
#pragma unroll
        for (int i = 0; i < 4; i++)
#pragma unroll
            for (int j = 0; j < 4; j++) { float lo, hi; upk2(s2[i][j], lo, hi); s[i][j] = lo + hi; }

        {
            const uint4 mk = *(const uint4*)&mask[(size_t)b * SS + kb * 64 + tx * 4];
            const float mb0 = mk.x ? 0.f : -1e30f;
            const float mb1 = mk.y ? 0.f : -1e30f;
            const float mb2 = mk.z ? 0.f : -1e30f;
            const float mb3 = mk.w ? 0.f : -1e30f;
#pragma unroll
            for (int i = 0; i < 4; i++) { s[i][0] += mb0; s[i][1] += mb1; s[i][2] += mb2; s[i][3] += mb3; }
        }

#pragma unroll
        for (int i = 0; i < 4; i++) {
            float rm = fmaxf(fmaxf(s[i][0], s[i][1]), fmaxf(s[i][2], s[i][3]));
            rm = fmaxf(rm, __shfl_xor_sync(0xffffffffu, rm, 1));
            rm = fmaxf(rm, __shfl_xor_sync(0xffffffffu, rm, 2));
            rm = fmaxf(rm, __shfl_xor_sync(0xffffffffu, rm, 4));
            rm = fmaxf(rm, __shfl_xor_sync(0xffffffffu, rm, 8));
            const float nm = fmaxf(m_i[i], rm);
            const float corr = __expf(m_i[i] - nm);
            float rs = 0.f;
#pragma unroll
            for (int j = 0; j < 4; j++) { s[i][j] = __expf(s[i][j] - nm); rs += s[i][j]; }
            rs += __shfl_xor_sync(0xffffffffu, rs, 1);
            rs += __shfl_xor_sync(0xffffffffu, rs, 2);
            rs += __shfl_xor_sync(0xffffffffu, rs, 4);
            rs += __shfl_xor_sync(0xffffffffu, rs, 8);
            l_i[i] = l_i[i] * corr + rs;
            m_i[i] = nm;
            const u64 cp = dup2(corr);
            o2[i][0] = f2mul(o2[i][0], cp);
            o2[i][1] = f2mul(o2[i][1], cp);
        }

        __syncthreads();
#pragma unroll
        for (int i = 0; i < 4; i++)
            *(float4*)&sK[SWF(ty * 4 + i, tx)] = make_float4(s[i][0], s[i][1], s[i][2], s[i][3]);
        __syncthreads();

#pragma unroll 4
        for (int kc = 0; kc < 16; kc++) {
            float pvv[4][4];
#pragma unroll
            for (int i = 0; i < 4; i++) *(float4*)pvv[i] = *(const float4*)&sK[SWF(ty * 4 + i, kc)];
            ulonglong2 vv[4];
#pragma unroll
            for (int jj = 0; jj < 4; jj++) vv[jj] = *(const ulonglong2*)&sV[SWF(kc * 4 + jj, tx)];
#pragma unroll
            for (int jj = 0; jj < 4; jj++)
#pragma unroll
                for (int i = 0; i < 4; i++) {
                    const u64 p = dup2(pvv[i][jj]);
                    o2[i][0] = f2fma(p, vv[jj].x, o2[i][0]);
                    o2[i][1] = f2fma(p, vv[jj].y, o2[i][1]);
                }
        }
    }

#pragma unroll
    for (int i = 0; i < 4; i++) {
        const float inv = 1.f / l_i[i];
        float o0, o1, o2f, o3;
        upk2(o2[i][0], o0, o1);
        upk2(o2[i][1], o2f, o3);
        const size_t row = (size_t)b * SS + q0 + ty * 4 + i;
        *(float4*)&O[row * EMB + h * HDIM + tx * 4] =
            make_float4(o0 * inv, o1 * inv, o2f * inv, o3 * inv);
    }
}

// ---------------- launch ----------------
extern "C" void kernel_launch(void* const* d_in, const int* in_sizes, int n_in,
                              void* d_out, int out_size)
{
    const float* query = (const float*)d_in[0];
    const float* key   = (const float*)d_in[1];
    const float* value = (const float*)d_in[2];
    const unsigned int* mask = (const unsigned int*)d_in[3];
    const float* Wq = (const float*)d_in[4];
    const float* bq = (const float*)d_in[5];
    const float* Wk = (const float*)d_in[6];
    const float* bk = (const float*)d_in[7];
    const float* Wv = (const float*)d_in[8];
    const float* bv = (const float*)d_in[9];
    const float* Wo = (const float*)d_in[10];
    const float* bo = (const float*)d_in[11];
    float* out = (float*)d_out;

    float *q, *k, *v, *attn;
    __nv_bfloat16 *ahi, *alo, *wthi, *wtlo;
    cudaGetSymbolAddress((void**)&q,    g_q);
    cudaGetSymbolAddress((void**)&k,    g_k);
    cudaGetSymbolAddress((void**)&v,    g_v);
    cudaGetSymbolAddress((void**)&attn, g_attn);
    cudaGetSymbolAddress((void**)&ahi,  g_ahi);
    cudaGetSymbolAddress((void**)&alo,  g_alo);
    cudaGetSymbolAddress((void**)&wthi, g_wthi);
    cudaGetSymbolAddress((void**)&wtlo, g_wtlo);

    cudaFuncSetAttribute(gemm_mma, cudaFuncAttributeMaxDynamicSharedMemorySize, GEMM_SMEM);

    const dim3 ggrid(EMB / 128, MROWS / 128);   // (8, 64)
    const dim3 tgrid(EMB / 32, EMB / 32), tblk(32, 8);
    const int n4 = MROWS * EMB / 4;
    const float qscale = 0.125f;                // 1/sqrt(64)

    split_bf16<<<2048, 256>>>(query, ahi, alo, n4);
    transpose_split<<<tgrid, tblk>>>(Wq, wthi, wtlo);
    gemm_mma<<<ggrid, 256, GEMM_SMEM>>>(ahi, alo, wthi, wtlo, bq, q, qscale, 1);

    split_bf16<<<2048, 256>>>(key, ahi, alo, n4);
    transpose_split<<<tgrid, tblk>>>(Wk, wthi, wtlo);
    gemm_mma<<<ggrid, 256, GEMM_SMEM>>>(ahi, alo, wthi, wtlo, bk, k, 1.0f, 1);

    split_bf16<<<2048, 256>>>(value, ahi, alo, n4);
    transpose_split<<<tgrid, tblk>>>(Wv, wthi, wtlo);
    gemm_mma<<<ggrid, 256, GEMM_SMEM>>>(ahi, alo, wthi, wtlo, bv, v, 1.0f, 1);

    flash_attn64<<<dim3(SS / 64, BB * HEADS), 256>>>(q, k, v, mask, attn);

    split_bf16<<<2048, 256>>>(attn, ahi, alo, n4);
    transpose_split<<<tgrid, tblk>>>(Wo, wthi, wtlo);
    gemm_mma<<<ggrid, 256, GEMM_SMEM>>>(ahi, alo, wthi, wtlo, bo, out, 1.0f, 0);
}

// round 15
// speedup vs baseline: 5.4000x; 2.1371x over previous
#include <cuda_runtime.h>
#include <cuda_bf16.h>
#include <math.h>

#define BB 4
#define SS 2048
#define EMB 1024
#define HEADS 16
#define HDIM 64
#define MROWS (BB * SS)   // 8192

typedef unsigned long long u64;
typedef unsigned int u32;

#define SWZ(o) ((o) ^ (((o) >> 3) & 0x70))   // SW128 byte swizzle

// ---------------- baseline async + mma helpers (sm_103-safe) ----------------
__device__ __forceinline__ u32 smem_u32(const void* p) {
    u32 a; asm("{ .reg .u64 t; cvta.to.shared.u64 t, %1; cvt.u32.u64 %0, t; }" : "=r"(a) : "l"(p));
    return a;
}
__device__ __forceinline__ void cp16(u32 dst, const void* src) {
    asm volatile("cp.async.cg.shared.global [%0], [%1], 16;" :: "r"(dst), "l"(src) : "memory");
}
__device__ __forceinline__ void cp_commit() { asm volatile("cp.async.commit_group;" ::: "memory"); }
__device__ __forceinline__ void cp_wait2()  { asm volatile("cp.async.wait_group 2;"  ::: "memory"); }
__device__ __forceinline__ void cp_wait1()  { asm volatile("cp.async.wait_group 1;"  ::: "memory"); }
__device__ __forceinline__ void cp_wait0()  { asm volatile("cp.async.wait_group 0;"  ::: "memory"); }

__device__ __forceinline__ void ldm_x4(u32* r, u32 addr) {
    asm volatile("ldmatrix.sync.aligned.m8n8.x4.shared.b16 {%0,%1,%2,%3}, [%4];"
        : "=r"(r[0]), "=r"(r[1]), "=r"(r[2]), "=r"(r[3]) : "r"(addr));
}
__device__ __forceinline__ void ldm_x2(u32* r, u32 addr) {
    asm volatile("ldmatrix.sync.aligned.m8n8.x2.shared.b16 {%0,%1}, [%2];"
        : "=r"(r[0]), "=r"(r[1]) : "r"(addr));
}
__device__ __forceinline__ void ldm_x2t(u32* r, u32 addr) {
    asm volatile("ldmatrix.sync.aligned.m8n8.x2.trans.shared.b16 {%0,%1}, [%2];"
        : "=r"(r[0]), "=r"(r[1]) : "r"(addr));
}
__device__ __forceinline__ void mma_bf16(float* c, const u32* a, const u32* b) {
    asm volatile(
        "mma.sync.aligned.m16n8k16.row.col.f32.bf16.bf16.f32 "
        "{%0,%1,%2,%3}, {%4,%5,%6,%7}, {%8,%9}, {%0,%1,%2,%3};"
        : "+f"(c[0]), "+f"(c[1]), "+f"(c[2]), "+f"(c[3])
        : "r"(a[0]), "r"(a[1]), "r"(a[2]), "r"(a[3]), "r"(b[0]), "r"(b[1]));
}
// pack (s0, s1) -> bf16x2 hi + bf16x2 residual lo
__device__ __forceinline__ void pack_hilo(float s0, float s1, u32& ph, u32& pl) {
    u32 h; asm("cvt.rn.bf16x2.f32 %0, %1, %2;" : "=r"(h) : "f"(s1), "f"(s0));
    const float h0 = __uint_as_float(h << 16);
    const float h1 = __uint_as_float(h & 0xffff0000u);
    u32 l; asm("cvt.rn.bf16x2.f32 %0, %1, %2;" : "=r"(l) : "f"(s1 - h1), "f"(s0 - h0));
    ph = h; pl = l;
}

// ---------------- scratch ----------------
__device__ __nv_bfloat16 g_ahi[MROWS * EMB];
__device__ __nv_bfloat16 g_alo[MROWS * EMB];
__device__ __nv_bfloat16 g_wthi[EMB * EMB];
__device__ __nv_bfloat16 g_wtlo[EMB * EMB];
__device__ __nv_bfloat16 g_qhi[MROWS * EMB];
__device__ __nv_bfloat16 g_qlo[MROWS * EMB];
__device__ __nv_bfloat16 g_khi[MROWS * EMB];
__device__ __nv_bfloat16 g_klo[MROWS * EMB];
__device__ __nv_bfloat16 g_vhi[MROWS * EMB];
__device__ __nv_bfloat16 g_vlo[MROWS * EMB];

// ---------------- bf16 split preps ----------------
__device__ __forceinline__ unsigned short bfbits(float x) {
    __nv_bfloat16 h = __float2bfloat16(x);
    return reinterpret_cast<unsigned short&>(h);
}
__device__ __forceinline__ float bfval(unsigned short b) {
    __nv_bfloat16 h = reinterpret_cast<__nv_bfloat16&>(b);
    return __bfloat162float(h);
}

__global__ __launch_bounds__(256) void split_bf16(
    const float* __restrict__ x, __nv_bfloat16* __restrict__ hi,
    __nv_bfloat16* __restrict__ lo, int n4)
{
    int i = blockIdx.x * blockDim.x + threadIdx.x;
    const int stride = gridDim.x * blockDim.x;
    for (; i < n4; i += stride) {
        const float4 v = ((const float4*)x)[i];
        unsigned short h0 = bfbits(v.x), h1 = bfbits(v.y), h2 = bfbits(v.z), h3 = bfbits(v.w);
        unsigned short l0 = bfbits(v.x - bfval(h0)), l1 = bfbits(v.y - bfval(h1));
        unsigned short l2 = bfbits(v.z - bfval(h2)), l3 = bfbits(v.w - bfval(h3));
        ((uint2*)hi)[i] = make_uint2((u32)h0 | ((u32)h1 << 16), (u32)h2 | ((u32)h3 << 16));
        ((uint2*)lo)[i] = make_uint2((u32)l0 | ((u32)l1 << 16), (u32)l2 | ((u32)l3 << 16));
    }
}

__global__ void transpose_split(
    const float* __restrict__ W, __nv_bfloat16* __restrict__ hi,
    __nv_bfloat16* __restrict__ lo)
{
    __shared__ float t[32][33];
    const int k0 = blockIdx.y * 32, n0 = blockIdx.x * 32;
    const int x = threadIdx.x, y0 = threadIdx.y;
#pragma unroll
    for (int i = 0; i < 4; i++) t[y0 + i * 8][x] = W[(size_t)(k0 + y0 + i * 8) * EMB + n0 + x];
    __syncthreads();
#pragma unroll
    for (int i = 0; i < 4; i++) {
        const int nn = y0 + i * 8;
        const float v = t[x][nn];
        const unsigned short h = bfbits(v);
        const unsigned short l = bfbits(v - bfval(h));
        hi[(size_t)(n0 + nn) * EMB + k0 + x] = reinterpret_cast<const __nv_bfloat16&>(h);
        lo[(size_t)(n0 + nn) * EMB + k0 + x] = reinterpret_cast<const __nv_bfloat16&>(l);
    }
}

// ---------------- mma.sync GEMM (bf16x3) ----------------
#define GEMM_NIT 16
#define STAGE_BYTES 65536
#define GEMM_SMEM (2 * STAGE_BYTES)

__device__ __forceinline__ void gemm_load_stage(
    u32 st, const __nv_bfloat16* __restrict__ Ahi, const __nv_bfloat16* __restrict__ Alo,
    const __nv_bfloat16* __restrict__ Bhi, const __nv_bfloat16* __restrict__ Blo,
    int m0, int n0, int k0, int tid)
{
#pragma unroll
    for (int i = 0; i < 4; i++) {
        const int c = tid + i * 256;
        const int row = c >> 3, col16 = c & 7;
        const u32 sw = (u32)SWZ(row * 128 + col16 * 16);
        const size_t ga = (size_t)(m0 + row) * EMB + k0 + col16 * 8;
        const size_t gb = (size_t)(n0 + row) * EMB + k0 + col16 * 8;
        cp16(st +     0 + sw, Ahi + ga);
        cp16(st + 16384 + sw, Alo + ga);
        cp16(st + 32768 + sw, Bhi + gb);
        cp16(st + 49152 + sw, Blo + gb);
    }
}

__global__ __launch_bounds__(256)
void gemm_mma(const __nv_bfloat16* __restrict__ Ahi, const __nv_bfloat16* __restrict__ Alo,
              const __nv_bfloat16* __restrict__ Bhi, const __nv_bfloat16* __restrict__ Blo,
              const float* __restrict__ bias, float* __restrict__ C,
              __nv_bfloat16* __restrict__ Chi, __nv_bfloat16* __restrict__ Clo,
              float scale, int split_mode)
{
    extern __shared__ __align__(1024) char smem[];
    const u32 sb = smem_u32(smem);
    const int tid = threadIdx.x;
    const int lane = tid & 31, wid = tid >> 5;
    const int wm = wid & 1, wn = wid >> 1;
    const int m0 = blockIdx.y * 128, n0 = blockIdx.x * 128;

    float acc[4][4][4];
#pragma unroll
    for (int mt = 0; mt < 4; mt++)
#pragma unroll
        for (int nt = 0; nt < 4; nt++)
#pragma unroll
            for (int e = 0; e < 4; e++) acc[mt][nt][e] = 0.f;

    const int a_row = (lane & 15), a_kb = (lane >> 4) * 16;
    const int b_row = (lane & 7),  b_kb = ((lane >> 3) & 1) * 16;

    gemm_load_stage(sb,               Ahi, Alo, Bhi, Blo, m0, n0, 0,  tid); cp_commit();
    gemm_load_stage(sb + STAGE_BYTES, Ahi, Alo, Bhi, Blo, m0, n0, 64, tid); cp_commit();

    for (int it = 0; it < GEMM_NIT; it++) {
        const u32 stg = sb + (it & 1) * STAGE_BYTES;
        if (it >= GEMM_NIT - 2) cp_wait0(); else cp_wait1();
        __syncthreads();

        const u32 sAh = stg, sAl = stg + 16384, sBh = stg + 32768, sBl = stg + 49152;
#pragma unroll
        for (int ks = 0; ks < 4; ks++) {
            u32 ah[4][4], al[4][4], bh[4][2], bl[4][2];
#pragma unroll
            for (int mt = 0; mt < 4; mt++) {
                const u32 off = (u32)SWZ((wm * 64 + mt * 16 + a_row) * 128 + ks * 32 + a_kb);
                ldm_x4(ah[mt], sAh + off);
                ldm_x4(al[mt], sAl + off);
            }
#pragma unroll
            for (int nt = 0; nt < 4; nt++) {
                const u32 off = (u32)SWZ((wn * 32 + nt * 8 + b_row) * 128 + ks * 32 + b_kb);
                ldm_x2(bh[nt], sBh + off);
                ldm_x2(bl[nt], sBl + off);
            }
#pragma unroll
            for (int mt = 0; mt < 4; mt++)
#pragma unroll
                for (int nt = 0; nt < 4; nt++) {
                    mma_bf16(acc[mt][nt], ah[mt], bh[nt]);
                    mma_bf16(acc[mt][nt], ah[mt], bl[nt]);
                    mma_bf16(acc[mt][nt], al[mt], bh[nt]);
                }
        }
        __syncthreads();
        if (it + 2 < GEMM_NIT) {
            gemm_load_stage(stg, Ahi, Alo, Bhi, Blo, m0, n0, (it + 2) * 64, tid);
            cp_commit();
        }
    }

#pragma unroll
    for (int mt = 0; mt < 4; mt++) {
        const int r0 = m0 + wm * 64 + mt * 16 + (lane >> 2);
#pragma unroll
        for (int nt = 0; nt < 4; nt++) {
            const int cc = n0 + wn * 32 + nt * 8 + (lane & 3) * 2;
            const float2 bb = *(const float2*)&bias[cc];
#pragma unroll
            for (int half = 0; half < 2; half++) {
                const int m = r0 + half * 8;
                const float v0 = (acc[mt][nt][half * 2 + 0] + bb.x) * scale;
                const float v1 = (acc[mt][nt][half * 2 + 1] + bb.y) * scale;
                if (split_mode) {   // bf16 hi/lo, (B,H,S,D) layout
                    const int b = m >> 11, s2 = m & 2047;
                    const int h = cc >> 6, dd = cc & 63;
                    u32 ph, pl; pack_hilo(v0, v1, ph, pl);
                    const size_t off = (((size_t)(b * HEADS + h) * SS) + s2) * HDIM + dd;
                    *(u32*)&Chi[off] = ph;
                    *(u32*)&Clo[off] = pl;
                } else {
                    *(float2*)&C[(size_t)m * EMB + cc] = make_float2(v0, v1);
                }
            }
        }
    }
}

// ---------------- flash attention via mma.sync (bf16x3) ----------------
// CTA: 128 q-rows x (b,h). 8 warps, warp w owns q rows [w*16, w*16+16).
// smem: Qhi/Qlo 32K + 2 stages x (Khi,Klo,Vhi,Vlo 8K each) = 96K.
#define FA_SMEM (32768 + 65536)

__device__ __forceinline__ void fa_load_stage(
    u32 st, const __nv_bfloat16* Kh, const __nv_bfloat16* Kl,
    const __nv_bfloat16* Vh, const __nv_bfloat16* Vl, size_t gbase, int tid)
{
#pragma unroll
    for (int i = 0; i < 2; i++) {
        const int c = tid + i * 256;              // 0..511
        const int row = c >> 3, col16 = c & 7;
        const u32 sw = (u32)SWZ(row * 128 + col16 * 16);
        const size_t g = gbase + (size_t)row * HDIM + col16 * 8;
        cp16(st +     0 + sw, Kh + g);
        cp16(st +  8192 + sw, Kl + g);
        cp16(st + 16384 + sw, Vh + g);
        cp16(st + 24576 + sw, Vl + g);
    }
}

__global__ __launch_bounds__(256, 1)
void flash_mma(const __nv_bfloat16* __restrict__ Qh_, const __nv_bfloat16* __restrict__ Ql_,
               const __nv_bfloat16* __restrict__ Kh_, const __nv_bfloat16* __restrict__ Kl_,
               const __nv_bfloat16* __restrict__ Vh_, const __nv_bfloat16* __restrict__ Vl_,
               const u32* __restrict__ mask,
               __nv_bfloat16* __restrict__ Ohi, __nv_bfloat16* __restrict__ Olo)
{
    extern __shared__ __align__(1024) char smem[];
    __shared__ float mb[2][64];
    const u32 sb = smem_u32(smem);
    const int tid = threadIdx.x;
    const int lane = tid & 31, w = tid >> 5;
    const int bh = blockIdx.y, b = bh >> 4, h = bh & 15;
    const int q0 = blockIdx.x * 128;

    const size_t qbase  = ((size_t)bh * SS + q0) * HDIM;
    const size_t kvbase = (size_t)bh * SS * HDIM;
    const u32 sQh = sb, sQl = sb + 16384;
    const u32 stg0 = sb + 32768, stg1 = sb + 65536;

    // Q tile loads (hi+lo): 2048 chunks / 256 thr = 8 each
#pragma unroll
    for (int i = 0; i < 4; i++) {
        const int c = tid + i * 256;
        const int row = c >> 3, col16 = c & 7;
        const u32 sw = (u32)SWZ(row * 128 + col16 * 16);
        const size_t g = qbase + (size_t)row * HDIM + col16 * 8;
        cp16(sQh + sw, Qh_ + g);
        cp16(sQl + sw, Ql_ + g);
    }
    cp_commit();
    fa_load_stage(stg0, Kh_, Kl_, Vh_, Vl_, kvbase, tid);          cp_commit();
    if (tid < 64) mb[0][tid] = mask[(size_t)b * SS + tid] ? 0.f : -1e30f;
    fa_load_stage(stg1, Kh_, Kl_, Vh_, Vl_, kvbase + 64 * HDIM, tid); cp_commit();
    if (tid < 64) mb[1][tid] = mask[(size_t)b * SS + 64 + tid] ? 0.f : -1e30f;

    cp_wait2();     // Q group done
    __syncthreads();

    // Q fragments (loop-invariant)
    u32 qh[4][4], ql[4][4];
    const int a_row = (lane & 15), a_kb = (lane >> 4) * 16;
#pragma unroll
    for (int ks = 0; ks < 4; ks++) {
        const u32 off = (u32)SWZ((w * 16 + a_row) * 128 + ks * 32 + a_kb);
        ldm_x4(qh[ks], sQh + off);
        ldm_x4(ql[ks], sQl + off);
    }

    float m_i[2] = { -INFINITY, -INFINITY }, l_i[2] = { 0.f, 0.f };
    float o[8][4];
#pragma unroll
    for (int nt = 0; nt < 8; nt++)
#pragma unroll
        for (int e = 0; e < 4; e++) o[nt][e] = 0.f;

    const int b_row = (lane & 7), b_kb = ((lane >> 3) & 1) * 16;

    for (int kb = 0; kb < 32; kb++) {
        const int st = kb & 1;
        const u32 stg = st ? stg1 : stg0;
        if (kb >= 30) cp_wait0(); else cp_wait1();
        __syncthreads();

        const u32 sKh = stg, sKl = stg + 8192, sVh = stg + 16384, sVl = stg + 24576;

        // --- QK^T (3-pass bf16x3), scores in fp32 acc regs ---
        float s[8][4];
#pragma unroll
        for (int nt = 0; nt < 8; nt++)
#pragma unroll
            for (int e = 0; e < 4; e++) s[nt][e] = 0.f;

#pragma unroll
        for (int ks = 0; ks < 4; ks++) {
            u32 kh[8][2], kl[8][2];
#pragma unroll
            for (int nt = 0; nt < 8; nt++) {
                const u32 off = (u32)SWZ((nt * 8 + b_row) * 128 + ks * 32 + b_kb);
                ldm_x2(kh[nt], sKh + off);
                ldm_x2(kl[nt], sKl + off);
            }
#pragma unroll
            for (int nt = 0; nt < 8; nt++) {
                mma_bf16(s[nt], qh[ks], kh[nt]);
                mma_bf16(s[nt], qh[ks], kl[nt]);
                mma_bf16(s[nt], ql[ks], kh[nt]);
            }
        }

        // --- mask bias ---
#pragma unroll
        for (int nt = 0; nt < 8; nt++) {
            const int kc = nt * 8 + (lane & 3) * 2;
            const float c0 = mb[st][kc], c1 = mb[st][kc + 1];
            s[nt][0] += c0; s[nt][1] += c1; s[nt][2] += c0; s[nt][3] += c1;
        }

        // --- online softmax (rows r=lane>>2 and r+8; row group = 4 lanes) ---
        float rm0 = -INFINITY, rm1 = -INFINITY;
#pragma unroll
        for (int nt = 0; nt < 8; nt++) {
            rm0 = fmaxf(rm0, fmaxf(s[nt][0], s[nt][1]));
            rm1 = fmaxf(rm1, fmaxf(s[nt][2], s[nt][3]));
        }
        rm0 = fmaxf(rm0, __shfl_xor_sync(0xffffffffu, rm0, 1));
        rm0 = fmaxf(rm0, __shfl_xor_sync(0xffffffffu, rm0, 2));
        rm1 = fmaxf(rm1, __shfl_xor_sync(0xffffffffu, rm1, 1));
        rm1 = fmaxf(rm1, __shfl_xor_sync(0xffffffffu, rm1, 2));
        const float nm0 = fmaxf(m_i[0], rm0), nm1 = fmaxf(m_i[1], rm1);
        const float corr0 = __expf(m_i[0] - nm0), corr1 = __expf(m_i[1] - nm1);
        float rs0 = 0.f, rs1 = 0.f;
#pragma unroll
        for (int nt = 0; nt < 8; nt++) {
            s[nt][0] = __expf(s[nt][0] - nm0); s[nt][1] = __expf(s[nt][1] - nm0);
            s[nt][2] = __expf(s[nt][2] - nm1); s[nt][3] = __expf(s[nt][3] - nm1);
            rs0 += s[nt][0] + s[nt][1];
            rs1 += s[nt][2] + s[nt][3];
        }
        rs0 += __shfl_xor_sync(0xffffffffu, rs0, 1);
        rs0 += __shfl_xor_sync(0xffffffffu, rs0, 2);
        rs1 += __shfl_xor_sync(0xffffffffu, rs1, 1);
        rs1 += __shfl_xor_sync(0xffffffffu, rs1, 2);
        l_i[0] = l_i[0] * corr0 + rs0; m_i[0] = nm0;
        l_i[1] = l_i[1] * corr1 + rs1; m_i[1] = nm1;
#pragma unroll
        for (int nt = 0; nt < 8; nt++) {
            o[nt][0] *= corr0; o[nt][1] *= corr0;
            o[nt][2] *= corr1; o[nt][3] *= corr1;
        }

        // --- PV: P acc frags -> A frags (hi/lo), V via ldmatrix.trans ---
#pragma unroll
        for (int kt = 0; kt < 4; kt++) {
            u32 Ph[4], Pl[4];
            pack_hilo(s[2 * kt][0],     s[2 * kt][1],     Ph[0], Pl[0]);
            pack_hilo(s[2 * kt][2],     s[2 * kt][3],     Ph[1], Pl[1]);
            pack_hilo(s[2 * kt + 1][0], s[2 * kt + 1][1], Ph[2], Pl[2]);
            pack_hilo(s[2 * kt + 1][2], s[2 * kt + 1][3], Ph[3], Pl[3]);
            const u32 voff_row = kt * 16 + (lane & 15);
#pragma unroll
            for (int nt = 0; nt < 8; nt++) {
                u32 vh[2], vl[2];
                const u32 off = (u32)SWZ(voff_row * 128 + nt * 16);
                ldm_x2t(vh, sVh + off);
                ldm_x2t(vl, sVl + off);
                mma_bf16(o[nt], Ph, vh);
                mma_bf16(o[nt], Ph, vl);
                mma_bf16(o[nt], Pl, vh);
            }
        }

        __syncthreads();
        if (kb + 2 < 32) {
            fa_load_stage(stg, Kh_, Kl_, Vh_, Vl_, kvbase + (size_t)(kb + 2) * 64 * HDIM, tid);
            cp_commit();
            if (tid < 64) mb[st][tid] = mask[(size_t)b * SS + (kb + 2) * 64 + tid] ? 0.f : -1e30f;
        }
    }

    // --- epilogue: normalize, split to bf16 hi/lo, write (B,S,E) ---
    const float inv0 = 1.f / l_i[0], inv1 = 1.f / l_i[1];
    const size_t row0 = (size_t)b * SS + q0 + w * 16 + (lane >> 2);
    const size_t row1 = row0 + 8;
#pragma unroll
    for (int nt = 0; nt < 8; nt++) {
        const int col = h * HDIM + nt * 8 + (lane & 3) * 2;
        u32 ph, pl;
        pack_hilo(o[nt][0] * inv0, o[nt][1] * inv0, ph, pl);
        *(u32*)&Ohi[row0 * EMB + col] = ph;
        *(u32*)&Olo[row0 * EMB + col] = pl;
        pack_hilo(o[nt][2] * inv1, o[nt][3] * inv1, ph, pl);
        *(u32*)&Ohi[row1 * EMB + col] = ph;
        *(u32*)&Olo[row1 * EMB + col] = pl;
    }
}

// ---------------- launch ----------------
extern "C" void kernel_launch(void* const* d_in, const int* in_sizes, int n_in,
                              void* d_out, int out_size)
{
    const float* query = (const float*)d_in[0];
    const float* key   = (const float*)d_in[1];
    const float* value = (const float*)d_in[2];
    const u32*   mask  = (const u32*)d_in[3];
    const float* Wq = (const float*)d_in[4];
    const float* bq = (const float*)d_in[5];
    const float* Wk = (const float*)d_in[6];
    const float* bk = (const float*)d_in[7];
    const float* Wv = (const float*)d_in[8];
    const float* bv = (const float*)d_in[9];
    const float* Wo = (const float*)d_in[10];
    const float* bo = (const float*)d_in[11];
    float* out = (float*)d_out;

    __nv_bfloat16 *ahi, *alo, *wthi, *wtlo, *qhi, *qlo, *khi, *klo, *vhi, *vlo;
    cudaGetSymbolAddress((void**)&ahi,  g_ahi);
    cudaGetSymbolAddress((void**)&alo,  g_alo);
    cudaGetSymbolAddress((void**)&wthi, g_wthi);
    cudaGetSymbolAddress((void**)&wtlo, g_wtlo);
    cudaGetSymbolAddress((void**)&qhi,  g_qhi);
    cudaGetSymbolAddress((void**)&qlo,  g_qlo);
    cudaGetSymbolAddress((void**)&khi,  g_khi);
    cudaGetSymbolAddress((void**)&klo,  g_klo);
    cudaGetSymbolAddress((void**)&vhi,  g_vhi);
    cudaGetSymbolAddress((void**)&vlo,  g_vlo);

    cudaFuncSetAttribute(gemm_mma,  cudaFuncAttributeMaxDynamicSharedMemorySize, GEMM_SMEM);
    cudaFuncSetAttribute(flash_mma, cudaFuncAttributeMaxDynamicSharedMemorySize, FA_SMEM);

    const dim3 ggrid(EMB / 128, MROWS / 128);   // (8, 64)
    const dim3 tgrid(EMB / 32, EMB / 32), tblk(32, 8);
    const int n4 = MROWS * EMB / 4;
    const float qscale = 0.125f;                // 1/sqrt(64)

    split_bf16<<<2048, 256>>>(query, ahi, alo, n4);
    transpose_split<<<tgrid, tblk>>>(Wq, wthi, wtlo);
    gemm_mma<<<ggrid, 256, GEMM_SMEM>>>(ahi, alo, wthi, wtlo, bq, nullptr, qhi, qlo, qscale, 1);

    split_bf16<<<2048, 256>>>(key, ahi, alo, n4);
    transpose_split<<<tgrid, tblk>>>(Wk, wthi, wtlo);
    gemm_mma<<<ggrid, 256, GEMM_SMEM>>>(ahi, alo, wthi, wtlo, bk, nullptr, khi, klo, 1.0f, 1);

    split_bf16<<<2048, 256>>>(value, ahi, alo, n4);
    transpose_split<<<tgrid, tblk>>>(Wv, wthi, wtlo);
    gemm_mma<<<ggrid, 256, GEMM_SMEM>>>(ahi, alo, wthi, wtlo, bv, nullptr, vhi, vlo, 1.0f, 1);

    // flash: writes attn directly as bf16 hi/lo into ahi/alo (B,S,E)
    flash_mma<<<dim3(SS / 128, BB * HEADS), 256, FA_SMEM>>>(
        qhi, qlo, khi, klo, vhi, vlo, mask, ahi, alo);

    transpose_split<<<tgrid, tblk>>>(Wo, wthi, wtlo);
    gemm_mma<<<ggrid, 256, GEMM_SMEM>>>(ahi, alo, wthi, wtlo, bo, out, nullptr, nullptr, 1.0f, 0);
}